// round 10
// baseline (speedup 1.0000x reference)
#include <cuda_runtime.h>
#include <cuda_bf16.h>
#include <math.h>
#include <stdint.h>

#define NE    50000
#define DIM   200
#define BATCH 1024
#define EMAX  400000
#define RELD  40000
#define KPAD  256
#define NCHUNK 4
#define NPAD  256

// ---------------- scratch (zero-init => pad regions stay 0)
__device__ __align__(16) __nv_bfloat16 g_e0b[(size_t)NE*KPAD];
__device__ __align__(16) __nv_bfloat16 g_hrb[(size_t)BATCH*KPAD];
__device__ __align__(16) __nv_bfloat16 g_Wtb[(size_t)4*NPAD*KPAD];
__device__ __align__(16) __nv_bfloat16 g_Ub[(size_t)NE*DIM];
__device__ __align__(16) __nv_bfloat16 g_Vb[(size_t)NE*DIM];
__device__ __align__(16) float g_PL[(size_t)2*NE*8];
__device__ __align__(16) float g_X1[NE*DIM];
__device__ __align__(16) float g_X2[NE*DIM];
__device__ __align__(16) float g_MP[NE*DIM];
__device__ __align__(16) float g_E2[NE*DIM];
__device__ float g_NMASK[2*NE];
__device__ float g_NEWEDGE[EMAX];
__device__ int   g_rp_adj[NE+1];
__device__ int   g_rp_rw [NE+1];

// ================= helpers =================
__device__ __forceinline__ uint32_t smem_u32(const void* p) {
    uint32_t a;
    asm("{ .reg .u64 t; cvta.to.shared.u64 t, %1; cvt.u32.u64 %0, t; }" : "=r"(a) : "l"(p));
    return a;
}
#define SW128(o) ((o) ^ (((o) >> 3) & 0x70))

__device__ __forceinline__ void ldmx4(uint32_t* r, uint32_t addr) {
    asm volatile("ldmatrix.sync.aligned.m8n8.x4.shared.b16 {%0,%1,%2,%3}, [%4];"
        : "=r"(r[0]), "=r"(r[1]), "=r"(r[2]), "=r"(r[3]) : "r"(addr));
}
__device__ __forceinline__ void mma16816(float* c, const uint32_t* a, const uint32_t* b) {
    asm volatile("mma.sync.aligned.m16n8k16.row.col.f32.bf16.bf16.f32 "
        "{%0,%1,%2,%3}, {%4,%5,%6,%7}, {%8,%9}, {%0,%1,%2,%3};"
        : "+f"(c[0]), "+f"(c[1]), "+f"(c[2]), "+f"(c[3])
        : "r"(a[0]), "r"(a[1]), "r"(a[2]), "r"(a[3]), "r"(b[0]), "r"(b[1]));
}
__device__ __forceinline__ void cpa16(uint32_t dst, const void* src) {
    asm volatile("cp.async.cg.shared.global [%0], [%1], 16;" :: "r"(dst), "l"(src));
}
#define CPA_COMMIT() asm volatile("cp.async.commit_group;" ::: "memory")
#define CPA_WAIT(n)  asm volatile("cp.async.wait_group %0;" :: "n"(n) : "memory")

__device__ __forceinline__ float gate_fn(float logits, float u) {
    const float bias = 1e-4f;
    float eps = (2.f*bias - 1.f)*u + (1.f - bias);
    float t = 2.f*(__logf(eps) - __logf(1.f - eps) + logits);
    return 1.f/(1.f + __expf(-t));
}
__device__ __forceinline__ float warp_sum(float v) {
    #pragma unroll
    for (int o = 16; o; o >>= 1) v += __shfl_xor_sync(0xffffffffu, v, o);
    return v;
}

// ================= conversion kernels =================
__global__ void conv_e0_k(const float* __restrict__ e0) {
    int t = blockIdx.x*blockDim.x + threadIdx.x;
    if (t >= NE*50) return;
    int row = t/50, k = (t%50)*4;
    float4 v = *(const float4*)(e0 + (size_t)row*DIM + k);
    __nv_bfloat162 p0, p1;
    p0.x = __float2bfloat16(v.x); p0.y = __float2bfloat16(v.y);
    p1.x = __float2bfloat16(v.z); p1.y = __float2bfloat16(v.w);
    __nv_bfloat16* d = g_e0b + (size_t)row*KPAD + k;
    *(__nv_bfloat162*)(d)     = p0;
    *(__nv_bfloat162*)(d + 2) = p1;
}

__global__ void conv_w_k(const float* __restrict__ nW1, const float* __restrict__ eW1) {
    int inst = blockIdx.y;
    int t = blockIdx.x*blockDim.x + threadIdx.x;
    if (t >= DIM*DIM) return;
    const float* src;
    if (inst == 0)      src = nW1;
    else if (inst == 1) src = nW1 + RELD;
    else if (inst == 2) src = eW1 + 2*RELD;
    else                src = eW1 + 3*RELD;
    int n = t/DIM, k = t%DIM;
    g_Wtb[(size_t)inst*NPAD*KPAD + (size_t)n*KPAD + k] = __float2bfloat16(src[(size_t)k*DIM + n]);
}

// ================= HMMA machinery (R4 geometry) ============================
struct MmaCtx {
    int aAtom0, aAtom1, aLine0, aLine1, aKadd;
    int bAtom0, bAtom1, bLine0, bLine1, bKadd;
};
__device__ __forceinline__ void mma_setup(MmaCtx& cx, int tid) {
    int lane = tid & 31, i = lane >> 3, rr = lane & 7;
    int w = tid >> 5;
    int wm = w >> 1, wn = w & 1;
    int ar0 = wm*32 + (i&1)*8 + rr;
    int ar1 = ar0 + 16;
    int br0 = wn*32 + (i>>1)*8 + rr;
    int br1 = br0 + 16;
    cx.aAtom0 = (ar0>>3)*1024; cx.aLine0 = (ar0&7)*128;
    cx.aAtom1 = (ar1>>3)*1024; cx.aLine1 = (ar1&7)*128;
    cx.aKadd = (i>>1)*16;
    cx.bAtom0 = (br0>>3)*1024; cx.bLine0 = (br0&7)*128;
    cx.bAtom1 = (br1>>3)*1024; cx.bLine1 = (br1&7)*128;
    cx.bKadd = (i&1)*16;
}
__device__ __forceinline__ void mma_chunk(const MmaCtx& cx, uint32_t aA, uint32_t aB,
                                          float acc[2][4][4]) {
    #pragma unroll
    for (int ks = 0; ks < 4; ks++) {
        int kb = ks*32;
        uint32_t a0[4], a1[4], b0[4], b1[4];
        ldmx4(a0, aA + cx.aAtom0 + SW128(cx.aLine0 + kb + cx.aKadd));
        ldmx4(a1, aA + cx.aAtom1 + SW128(cx.aLine1 + kb + cx.aKadd));
        ldmx4(b0, aB + cx.bAtom0 + SW128(cx.bLine0 + kb + cx.bKadd));
        ldmx4(b1, aB + cx.bAtom1 + SW128(cx.bLine1 + kb + cx.bKadd));
        mma16816(acc[0][0], a0, b0);
        mma16816(acc[0][1], a0, b0 + 2);
        mma16816(acc[0][2], a0, b1);
        mma16816(acc[0][3], a0, b1 + 2);
        mma16816(acc[1][0], a1, b0);
        mma16816(acc[1][1], a1, b0 + 2);
        mma16816(acc[1][2], a1, b1);
        mma16816(acc[1][3], a1, b1 + 2);
    }
}
__device__ __forceinline__ void load_a128_async(uint32_t sA, const __nv_bfloat16* Ag,
                                                int row0, int rmax, int c, int tid) {
    #pragma unroll
    for (int i = 0; i < 4; i++) {
        int idx = tid + i*256;
        int r = idx >> 3, q = idx & 7;
        int gr = row0 + r; if (gr >= rmax) gr = 0;
        uint32_t off = (uint32_t)((r>>3)*1024) + SW128((uint32_t)((r&7)*128 + q*16));
        cpa16(sA + off, Ag + (size_t)gr*KPAD + c*64 + q*8);
    }
}
__device__ __forceinline__ void load_b64_async(uint32_t sB, const __nv_bfloat16* Bg,
                                               int row0, int rmax, int c, int tid) {
    #pragma unroll
    for (int i = 0; i < 2; i++) {
        int idx = tid + i*256;
        int r = idx >> 3, q = idx & 7;
        int gr = row0 + r; if (gr >= rmax) gr = 0;
        uint32_t off = (uint32_t)((r>>3)*1024) + SW128((uint32_t)((r&7)*128 + q*16));
        cpa16(sB + off, Bg + (size_t)gr*KPAD + c*64 + q*8);
    }
}

// ================= GEMM 1: e0 @ W (4 instances); node-gate dots fused ======
__global__ void __launch_bounds__(256) mm_e0w_k(
    const float* __restrict__ nb1, const float* __restrict__ eb1,
    const float* __restrict__ nW2)
{
    __shared__ __align__(1024) uint8_t sA[2][16384];
    __shared__ __align__(1024) uint8_t sB[2][8192];
    int bm = blockIdx.x, nt64 = blockIdx.y, inst = blockIdx.z;
    int tid = threadIdx.x;
    uint32_t aA0 = smem_u32(sA[0]), aA1 = smem_u32(sA[1]);
    uint32_t aB0 = smem_u32(sB[0]), aB1 = smem_u32(sB[1]);

    MmaCtx cx; mma_setup(cx, tid);
    float acc[2][4][4];
    #pragma unroll
    for (int a = 0; a < 2; a++)
        #pragma unroll
        for (int b = 0; b < 4; b++)
            #pragma unroll
            for (int q = 0; q < 4; q++) acc[a][b][q] = 0.f;

    const __nv_bfloat16* Bg = g_Wtb + (size_t)inst*NPAD*KPAD;

    load_a128_async(aA0, g_e0b, bm*128, NE, 0, tid);
    load_b64_async (aB0, Bg, nt64*64, NPAD, 0, tid);
    CPA_COMMIT();
    #pragma unroll
    for (int c = 0; c < NCHUNK; c++) {
        uint32_t curA = (c & 1) ? aA1 : aA0, curB = (c & 1) ? aB1 : aB0;
        if (c + 1 < NCHUNK) {
            uint32_t nxtA = ((c+1) & 1) ? aA1 : aA0, nxtB = ((c+1) & 1) ? aB1 : aB0;
            load_a128_async(nxtA, g_e0b, bm*128, NE, c+1, tid);
            load_b64_async (nxtB, Bg, nt64*64, NPAD, c+1, tid);
            CPA_COMMIT();
            CPA_WAIT(1);
        } else {
            CPA_WAIT(0);
        }
        __syncthreads();
        mma_chunk(cx, curA, curB, acc);
        __syncthreads();
    }

    int lane = tid & 31, w = tid >> 5;
    int wm = w >> 1, wn = w & 1;
    int mrow = lane >> 2, ncol = (lane & 3)*2;
    int nbase = nt64*64 + wn*32;

    if (inst < 2) {
        const float* bias = nb1 + inst*DIM;
        const float* W2 = nW2 + inst*DIM;
        int seg = nt64*2 + wn;
        #pragma unroll
        for (int mt = 0; mt < 2; mt++) {
            float p0 = 0.f, p1 = 0.f;
            #pragma unroll
            for (int nt = 0; nt < 4; nt++) {
                int n = nbase + nt*8 + ncol;
                float b0 = 0.f, b1v = 0.f, w0 = 0.f, w1 = 0.f;
                if (n < DIM)     { b0 = bias[n];   w0 = W2[n];   }
                if (n + 1 < DIM) { b1v = bias[n+1]; w1 = W2[n+1]; }
                p0 = fmaf(fmaxf(acc[mt][nt][0] + b0, 0.f), w0, p0);
                p0 = fmaf(fmaxf(acc[mt][nt][1] + b1v, 0.f), w1, p0);
                p1 = fmaf(fmaxf(acc[mt][nt][2] + b0, 0.f), w0, p1);
                p1 = fmaf(fmaxf(acc[mt][nt][3] + b1v, 0.f), w1, p1);
            }
            p0 += __shfl_xor_sync(0xffffffffu, p0, 1);
            p0 += __shfl_xor_sync(0xffffffffu, p0, 2);
            p1 += __shfl_xor_sync(0xffffffffu, p1, 1);
            p1 += __shfl_xor_sync(0xffffffffu, p1, 2);
            if ((lane & 3) == 0) {
                int m0 = bm*128 + wm*32 + mt*16 + mrow;
                if (m0 < NE)     g_PL[((size_t)inst*NE + m0)*8 + seg] = p0;
                if (m0 + 8 < NE) g_PL[((size_t)inst*NE + m0 + 8)*8 + seg] = p1;
            }
        }
    } else {
        __nv_bfloat16* C = (inst == 2) ? g_Ub : g_Vb;
        const float* bias = (inst == 3) ? (eb1 + DIM) : nullptr;
        #pragma unroll
        for (int mt = 0; mt < 2; mt++) {
            int m = bm*128 + wm*32 + mt*16 + mrow;
            if (m >= NE) continue;
            #pragma unroll
            for (int nt = 0; nt < 4; nt++) {
                int n = nbase + nt*8 + ncol;
                if (n >= DIM) continue;
                float b0 = bias ? bias[n] : 0.f, b1 = bias ? bias[n+1] : 0.f;
                __nv_bfloat162 p, q;
                p.x = __float2bfloat16(acc[mt][nt][0] + b0);
                p.y = __float2bfloat16(acc[mt][nt][1] + b1);
                q.x = __float2bfloat16(acc[mt][nt][2] + b0);
                q.y = __float2bfloat16(acc[mt][nt][3] + b1);
                *(__nv_bfloat162*)(C + (size_t)m*DIM + n) = p;
                if (m + 8 < NE) *(__nv_bfloat162*)(C + (size_t)(m+8)*DIM + n) = q;
            }
        }
    }
}

// gate finalize
__global__ void gate_fin_k(const float* __restrict__ nb2, const float* __restrict__ eps,
                           float* __restrict__ mask) {
    int idx = blockIdx.x*blockDim.x + threadIdx.x;
    if (idx >= 2*NE) return;
    int inst = idx / NE;
    const float* p = g_PL + (size_t)idx*8;
    float4 a = *(const float4*)p;
    float4 b = *(const float4*)(p + 4);
    float s = ((a.x + a.y) + (a.z + a.w)) + ((b.x + b.y) + (b.z + b.w));
    mask[idx] = gate_fn(s + nb2[inst], eps[idx]);
}

// ================= GEMM 2: scores ==========================================
__global__ void __launch_bounds__(256) scores_mm_k(float* __restrict__ out)
{
    __shared__ __align__(1024) uint8_t sA[2][16384];
    __shared__ __align__(1024) uint8_t sB[2][8192];
    int bx = blockIdx.x, by = blockIdx.y;
    int tid = threadIdx.x;
    uint32_t aA0 = smem_u32(sA[0]), aA1 = smem_u32(sA[1]);
    uint32_t aB0 = smem_u32(sB[0]), aB1 = smem_u32(sB[1]);

    MmaCtx cx; mma_setup(cx, tid);
    float acc[2][4][4];
    #pragma unroll
    for (int a = 0; a < 2; a++)
        #pragma unroll
        for (int b = 0; b < 4; b++)
            #pragma unroll
            for (int q = 0; q < 4; q++) acc[a][b][q] = 0.f;

    load_a128_async(aA0, g_hrb, by*128, BATCH, 0, tid);
    load_b64_async (aB0, g_e0b, bx*64, NE, 0, tid);
    CPA_COMMIT();
    #pragma unroll
    for (int c = 0; c < NCHUNK; c++) {
        uint32_t curA = (c & 1) ? aA1 : aA0, curB = (c & 1) ? aB1 : aB0;
        if (c + 1 < NCHUNK) {
            uint32_t nxtA = ((c+1) & 1) ? aA1 : aA0, nxtB = ((c+1) & 1) ? aB1 : aB0;
            load_a128_async(nxtA, g_hrb, by*128, BATCH, c+1, tid);
            load_b64_async (nxtB, g_e0b, bx*64, NE, c+1, tid);
            CPA_COMMIT();
            CPA_WAIT(1);
        } else {
            CPA_WAIT(0);
        }
        __syncthreads();
        mma_chunk(cx, curA, curB, acc);
        __syncthreads();
    }

    int lane = tid & 31, w = tid >> 5;
    int wm = w >> 1, wn = w & 1;
    int mrow = lane >> 2, ncol = (lane & 3)*2;
    #pragma unroll
    for (int mt = 0; mt < 2; mt++) {
        int m = by*128 + wm*32 + mt*16 + mrow;
        #pragma unroll
        for (int nt = 0; nt < 4; nt++) {
            int n = bx*64 + wn*32 + nt*8 + ncol;
            if (n < NE) {
                float2 v01, v23;
                v01.x = 1.f/(1.f + __expf(-acc[mt][nt][0]));
                v01.y = 1.f/(1.f + __expf(-acc[mt][nt][1]));
                v23.x = 1.f/(1.f + __expf(-acc[mt][nt][2]));
                v23.y = 1.f/(1.f + __expf(-acc[mt][nt][3]));
                *(float2*)(out + (size_t)m*NE + n) = v01;
                *(float2*)(out + (size_t)(m+8)*NE + n) = v23;
            }
        }
    }
}

// ================= support kernels =================
__global__ void rowptr_k(const int* __restrict__ row, int nnz, int* __restrict__ rowptr) {
    int n = blockIdx.x*blockDim.x + threadIdx.x;
    if (n > NE) return;
    int lo = 0, hi = nnz;
    while (lo < hi) { int mid = (lo+hi) >> 1; if (row[mid] < n) lo = mid+1; else hi = mid; }
    rowptr[n] = lo;
}

// edge gate: uint4 loads (bf16 row = 25 uint4)
__global__ void edge_gate_k(const int* __restrict__ row, const int* __restrict__ col,
                            const float* __restrict__ adj_val,
                            const float* __restrict__ W2, const float* __restrict__ b2,
                            const float* __restrict__ eps, float* __restrict__ new_edge,
                            int E) {
    int e = (blockIdx.x*blockDim.x + threadIdx.x) >> 5;
    int lane = threadIdx.x & 31;
    if (e >= E) return;
    int r = row[e], c = col[e];
    float acc = 0.f;
    if (lane < 25) {
        const uint4* ur = (const uint4*)(g_Ub + (size_t)r*DIM);
        const uint4* vr = (const uint4*)(g_Vb + (size_t)c*DIM);
        uint4 uu = __ldg(&ur[lane]);
        uint4 vv = __ldg(&vr[lane]);
        float4 w01 = __ldg((const float4*)(W2 + lane*8));
        float4 w23 = __ldg((const float4*)(W2 + lane*8 + 4));
        const __nv_bfloat162* up = (const __nv_bfloat162*)&uu;
        const __nv_bfloat162* vp = (const __nv_bfloat162*)&vv;
        const float* wp = (const float*)&w01;
        const float* wq = (const float*)&w23;
        #pragma unroll
        for (int t = 0; t < 2; t++) {
            __nv_bfloat162 a = up[t], b = vp[t];
            float h0 = fmaxf(__bfloat162float(a.x) + __bfloat162float(b.x), 0.f);
            float h1 = fmaxf(__bfloat162float(a.y) + __bfloat162float(b.y), 0.f);
            acc = fmaf(h0, wp[2*t], acc);
            acc = fmaf(h1, wp[2*t+1], acc);
        }
        #pragma unroll
        for (int t = 0; t < 2; t++) {
            __nv_bfloat162 a = up[2+t], b = vp[2+t];
            float h0 = fmaxf(__bfloat162float(a.x) + __bfloat162float(b.x), 0.f);
            float h1 = fmaxf(__bfloat162float(a.y) + __bfloat162float(b.y), 0.f);
            acc = fmaf(h0, wq[2*t], acc);
            acc = fmaf(h1, wq[2*t+1], acc);
        }
    }
    acc = warp_sum(acc);
    if (lane == 0) new_edge[e] = adj_val[e] * gate_fn(acc + b2[0], eps[e]);
}

// CSR SpMM, float4 gathers
__global__ void spmm_k(const int* __restrict__ rowptr, const int* __restrict__ col,
                       const float* __restrict__ val, const float* __restrict__ x,
                       float* __restrict__ y) {
    int r = (blockIdx.x*blockDim.x + threadIdx.x) >> 5;
    int lane = threadIdx.x & 31;
    if (r >= NE) return;
    float4 a0 = {0.f,0.f,0.f,0.f}, a1 = {0.f,0.f,0.f,0.f};
    bool p1 = (lane + 32) < 50;
    int s = rowptr[r], e = rowptr[r+1];
    for (int idx = s; idx < e; idx++) {
        int c = __ldg(&col[idx]);
        float v = __ldg(&val[idx]);
        const float4* xr = (const float4*)(x + (size_t)c*DIM);
        float4 g0 = __ldg(&xr[lane]);
        a0.x = fmaf(v, g0.x, a0.x); a0.y = fmaf(v, g0.y, a0.y);
        a0.z = fmaf(v, g0.z, a0.z); a0.w = fmaf(v, g0.w, a0.w);
        if (p1) {
            float4 g1 = __ldg(&xr[lane + 32]);
            a1.x = fmaf(v, g1.x, a1.x); a1.y = fmaf(v, g1.y, a1.y);
            a1.z = fmaf(v, g1.z, a1.z); a1.w = fmaf(v, g1.w, a1.w);
        }
    }
    float4* yr = (float4*)(y + (size_t)r*DIM);
    yr[lane] = a0;
    if (p1) yr[lane + 32] = a1;
}

// SpMM + mix fused, float4
__global__ void spmm_mix_k(const int* __restrict__ rowptr, const int* __restrict__ col,
                           const float* __restrict__ val, const float* __restrict__ x,
                           const float* __restrict__ mask, float* __restrict__ y) {
    int r = (blockIdx.x*blockDim.x + threadIdx.x) >> 5;
    int lane = threadIdx.x & 31;
    if (r >= NE) return;
    float4 a0 = {0.f,0.f,0.f,0.f}, a1 = {0.f,0.f,0.f,0.f};
    bool p1 = (lane + 32) < 50;
    int s = rowptr[r], e = rowptr[r+1];
    for (int idx = s; idx < e; idx++) {
        int c = __ldg(&col[idx]);
        float v = __ldg(&val[idx]);
        const float4* xr = (const float4*)(x + (size_t)c*DIM);
        float4 g0 = __ldg(&xr[lane]);
        a0.x = fmaf(v, g0.x, a0.x); a0.y = fmaf(v, g0.y, a0.y);
        a0.z = fmaf(v, g0.z, a0.z); a0.w = fmaf(v, g0.w, a0.w);
        if (p1) {
            float4 g1 = __ldg(&xr[lane + 32]);
            a1.x = fmaf(v, g1.x, a1.x); a1.y = fmaf(v, g1.y, a1.y);
            a1.z = fmaf(v, g1.z, a1.z); a1.w = fmaf(v, g1.w, a1.w);
        }
    }
    float m = mask[r], im = 1.f - m;
    const float4* xr = (const float4*)(x + (size_t)r*DIM);
    float4* yr = (float4*)(y + (size_t)r*DIM);
    float4 s0 = xr[lane];
    float4 o0;
    o0.x = m*s0.x + im*a0.x; o0.y = m*s0.y + im*a0.y;
    o0.z = m*s0.z + im*a0.z; o0.w = m*s0.w + im*a0.w;
    yr[lane] = o0;
    if (p1) {
        float4 s1 = xr[lane + 32];
        float4 o1;
        o1.x = m*s1.x + im*a1.x; o1.y = m*s1.y + im*a1.y;
        o1.z = m*s1.z + im*a1.z; o1.w = m*s1.w + im*a1.w;
        yr[lane + 32] = o1;
    }
}

// elementwise mix, float4
__global__ void mix_k(const float* __restrict__ x, const float* __restrict__ mp,
                      const float* __restrict__ mask, float* __restrict__ y) {
    int idx = blockIdx.x*blockDim.x + threadIdx.x;
    if (idx >= NE*50) return;
    int row = idx / 50;
    float m = mask[row], im = 1.f - m;
    float4 a = __ldg((const float4*)x + idx);
    float4 b = __ldg((const float4*)mp + idx);
    float4 o;
    o.x = m*a.x + im*b.x; o.y = m*a.y + im*b.y;
    o.z = m*a.z + im*b.z; o.w = m*a.w + im*b.w;
    ((float4*)y)[idx] = o;
}

// RESCAL -> bf16 hrb
__global__ void rescal_k(const float* __restrict__ e0, const float* __restrict__ rel_emb,
                         const int* __restrict__ sub, const int* __restrict__ rel) {
    int b = blockIdx.x;
    int j = threadIdx.x;
    __shared__ float ls[DIM];
    const float* lhs = e0 + (size_t)sub[b]*DIM;
    if (j < DIM) ls[j] = lhs[j];
    __syncthreads();
    if (j < DIM) {
        const float* R = rel_emb + (size_t)rel[b]*RELD;
        float acc = 0.f;
        #pragma unroll 4
        for (int k = 0; k < DIM; k++) acc = fmaf(ls[k], R[(size_t)k*DIM + j], acc);
        g_hrb[(size_t)b*KPAD + j] = __float2bfloat16(acc);
    }
}

// ================= launch ==================================================
extern "C" void kernel_launch(void* const* d_in, const int* in_sizes, int n_in,
                              void* d_out, int out_size) {
    const float* e0       = (const float*)d_in[0];
    const float* rel_emb  = (const float*)d_in[1];
    const float* nW1      = (const float*)d_in[2];
    const float* nb1      = (const float*)d_in[3];
    const float* nW2      = (const float*)d_in[4];
    const float* nb2      = (const float*)d_in[5];
    const float* eW1      = (const float*)d_in[6];
    const float* eb1      = (const float*)d_in[7];
    const float* eW2      = (const float*)d_in[8];
    const float* eb2      = (const float*)d_in[9];
    const int*   adj_row  = (const int*)d_in[10];
    const int*   adj_col  = (const int*)d_in[11];
    const float* adj_val  = (const float*)d_in[12];
    const int*   rw_row   = (const int*)d_in[13];
    const int*   rw_col   = (const int*)d_in[14];
    const float* rw_val   = (const float*)d_in[15];
    const float* node_eps = (const float*)d_in[16];
    const float* edge_eps = (const float*)d_in[17];
    const int*   sub      = (const int*)d_in[18];
    const int*   rel      = (const int*)d_in[19];

    int E   = in_sizes[10];
    int Erw = in_sizes[13];

    float* out        = (float*)d_out;
    float* out_scores = out;
    float* out_xnd    = out + (size_t)BATCH*NE;
    float* out_xed    = out_xnd + (size_t)NE*DIM;

    float *X1, *X2, *MP, *E2, *NMASK, *NEWEDGE;
    int *RPA, *RPR;
    cudaGetSymbolAddress((void**)&X1, g_X1);
    cudaGetSymbolAddress((void**)&X2, g_X2);
    cudaGetSymbolAddress((void**)&MP, g_MP);
    cudaGetSymbolAddress((void**)&E2, g_E2);
    cudaGetSymbolAddress((void**)&NMASK, g_NMASK);
    cudaGetSymbolAddress((void**)&NEWEDGE, g_NEWEDGE);
    cudaGetSymbolAddress((void**)&RPA, g_rp_adj);
    cudaGetSymbolAddress((void**)&RPR, g_rp_rw);

    static cudaStream_t s1 = nullptr, s2 = nullptr;
    static cudaEvent_t evFork0, evConv, evRw, evMM, evMP, evS1, evS2;
    if (!s1) {
        cudaStreamCreateWithFlags(&s1, cudaStreamNonBlocking);
        cudaStreamCreateWithFlags(&s2, cudaStreamNonBlocking);
        cudaEventCreateWithFlags(&evFork0, cudaEventDisableTiming);
        cudaEventCreateWithFlags(&evConv,  cudaEventDisableTiming);
        cudaEventCreateWithFlags(&evRw,    cudaEventDisableTiming);
        cudaEventCreateWithFlags(&evMM,    cudaEventDisableTiming);
        cudaEventCreateWithFlags(&evMP,    cudaEventDisableTiming);
        cudaEventCreateWithFlags(&evS1,    cudaEventDisableTiming);
        cudaEventCreateWithFlags(&evS2,    cudaEventDisableTiming);
    }

    const int SPB = (NE*32 + 255)/256;
    const int MT  = (NE + 127)/128;

    // ---- fork point ----
    cudaEventRecord(evFork0, 0);

    // ---- main stream: prep ----
    rowptr_k<<<(NE+1+255)/256, 256>>>(rw_row, Erw, RPR);
    cudaEventRecord(evRw, 0);
    rowptr_k<<<(NE+1+255)/256, 256>>>(adj_row, E, RPA);
    conv_e0_k<<<(NE*50 + 255)/256, 256>>>(e0);
    cudaEventRecord(evConv, 0);
    dim3 wgrid((DIM*DIM + 255)/256, 4);
    conv_w_k<<<wgrid, 256>>>(nW1, eW1);

    // ---- s1: rescal -> scores ----
    cudaStreamWaitEvent(s1, evFork0, 0);
    rescal_k<<<BATCH, 256, 0, s1>>>(e0, rel_emb, sub, rel);
    cudaStreamWaitEvent(s1, evConv, 0);
    dim3 sgrid((NE + 63)/64, BATCH/128);
    scores_mm_k<<<sgrid, 256, 0, s1>>>(out_scores);
    cudaEventRecord(evS1, s1);

    // ---- s2: edge-branch rw propagation ----
    cudaStreamWaitEvent(s2, evRw, 0);
    spmm_k<<<SPB, 256, 0, s2>>>(RPR, rw_col, rw_val, e0, MP);
    cudaEventRecord(evMP, s2);
    spmm_k<<<SPB, 256, 0, s2>>>(RPR, rw_col, rw_val, MP, E2);

    // ---- main: GEMM (fused node-gate dots) + finalize ----
    dim3 mgrid(MT, 4, 4);
    mm_e0w_k<<<mgrid, 256>>>(nb1, eb1, nW2);
    cudaEventRecord(evMM, 0);
    gate_fin_k<<<(2*NE + 255)/256, 256>>>(nb2, node_eps, NMASK);

    // ---- s2: edge gate + final edge spmm ----
    cudaStreamWaitEvent(s2, evMM, 0);
    edge_gate_k<<<(E*32 + 255)/256, 256, 0, s2>>>(adj_row, adj_col, adj_val,
                                                  eW2 + DIM, eb2 + 1, edge_eps + E, NEWEDGE, E);
    spmm_k<<<SPB, 256, 0, s2>>>(RPA, adj_col, NEWEDGE, E2, out_xed);
    cudaEventRecord(evS2, s2);

    // ---- main: node-drop branch ----
    cudaStreamWaitEvent(0, evMP, 0);
    mix_k<<<(NE*50 + 255)/256, 256>>>(e0, MP, NMASK, X1);
    spmm_k<<<SPB, 256>>>(RPA, adj_col, adj_val, X1, X2);
    spmm_mix_k<<<SPB, 256>>>(RPR, rw_col, rw_val, X2, NMASK + NE, X1);
    spmm_k<<<SPB, 256>>>(RPA, adj_col, adj_val, X1, out_xnd);

    // ---- join ----
    cudaStreamWaitEvent(0, evS1, 0);
    cudaStreamWaitEvent(0, evS2, 0);
}

// round 13
// speedup vs baseline: 1.0211x; 1.0211x over previous
#include <cuda_runtime.h>
#include <cuda_bf16.h>
#include <math.h>
#include <stdint.h>

#define NE    50000
#define DIM   200
#define BATCH 1024
#define EMAX  400000
#define RELD  40000
#define KPAD  256
#define NCHUNK 4
#define NPAD  256

// ---------------- scratch (zero-init => pad regions stay 0)
__device__ __align__(16) __nv_bfloat16 g_e0b[(size_t)NE*KPAD];
__device__ __align__(16) __nv_bfloat16 g_hrb[(size_t)BATCH*KPAD];
__device__ __align__(16) __nv_bfloat16 g_Wtb[(size_t)4*NPAD*KPAD];
__device__ __align__(16) __nv_bfloat16 g_Ub[(size_t)NE*DIM];
__device__ __align__(16) __nv_bfloat16 g_Vb[(size_t)NE*DIM];
__device__ __align__(16) float g_PL[(size_t)2*NE*8];
__device__ float g_X1[NE*DIM];
__device__ float g_X2[NE*DIM];
__device__ float g_MP[NE*DIM];
__device__ float g_E2[NE*DIM];
__device__ float g_NMASK[2*NE];
__device__ float g_NEWEDGE[EMAX];
__device__ int   g_rp_adj[NE+1];
__device__ int   g_rp_rw [NE+1];

// ================= helpers =================
__device__ __forceinline__ uint32_t smem_u32(const void* p) {
    uint32_t a;
    asm("{ .reg .u64 t; cvta.to.shared.u64 t, %1; cvt.u32.u64 %0, t; }" : "=r"(a) : "l"(p));
    return a;
}
#define SW128(o) ((o) ^ (((o) >> 3) & 0x70))

__device__ __forceinline__ void ldmx4(uint32_t* r, uint32_t addr) {
    asm volatile("ldmatrix.sync.aligned.m8n8.x4.shared.b16 {%0,%1,%2,%3}, [%4];"
        : "=r"(r[0]), "=r"(r[1]), "=r"(r[2]), "=r"(r[3]) : "r"(addr));
}
__device__ __forceinline__ void mma16816(float* c, const uint32_t* a, const uint32_t* b) {
    asm volatile("mma.sync.aligned.m16n8k16.row.col.f32.bf16.bf16.f32 "
        "{%0,%1,%2,%3}, {%4,%5,%6,%7}, {%8,%9}, {%0,%1,%2,%3};"
        : "+f"(c[0]), "+f"(c[1]), "+f"(c[2]), "+f"(c[3])
        : "r"(a[0]), "r"(a[1]), "r"(a[2]), "r"(a[3]), "r"(b[0]), "r"(b[1]));
}
__device__ __forceinline__ void cpa16(uint32_t dst, const void* src) {
    asm volatile("cp.async.cg.shared.global [%0], [%1], 16;" :: "r"(dst), "l"(src));
}
#define CPA_COMMIT() asm volatile("cp.async.commit_group;" ::: "memory")
#define CPA_WAIT(n)  asm volatile("cp.async.wait_group %0;" :: "n"(n) : "memory")

__device__ __forceinline__ float gate_fn(float logits, float u) {
    const float bias = 1e-4f;
    float eps = (2.f*bias - 1.f)*u + (1.f - bias);
    float t = 2.f*(__logf(eps) - __logf(1.f - eps) + logits);
    return 1.f/(1.f + __expf(-t));
}
__device__ __forceinline__ float warp_sum(float v) {
    #pragma unroll
    for (int o = 16; o; o >>= 1) v += __shfl_xor_sync(0xffffffffu, v, o);
    return v;
}

// ================= conversion kernels =================
__global__ void conv_e0_k(const float* __restrict__ e0) {
    int t = blockIdx.x*blockDim.x + threadIdx.x;
    if (t >= NE*50) return;
    int row = t/50, k = (t%50)*4;
    float4 v = *(const float4*)(e0 + (size_t)row*DIM + k);
    __nv_bfloat162 p0, p1;
    p0.x = __float2bfloat16(v.x); p0.y = __float2bfloat16(v.y);
    p1.x = __float2bfloat16(v.z); p1.y = __float2bfloat16(v.w);
    __nv_bfloat16* d = g_e0b + (size_t)row*KPAD + k;
    *(__nv_bfloat162*)(d)     = p0;
    *(__nv_bfloat162*)(d + 2) = p1;
}

__global__ void conv_w_k(const float* __restrict__ nW1, const float* __restrict__ eW1) {
    int inst = blockIdx.y;
    int t = blockIdx.x*blockDim.x + threadIdx.x;
    if (t >= DIM*DIM) return;
    const float* src;
    if (inst == 0)      src = nW1;
    else if (inst == 1) src = nW1 + RELD;
    else if (inst == 2) src = eW1 + 2*RELD;
    else                src = eW1 + 3*RELD;
    int n = t/DIM, k = t%DIM;
    g_Wtb[(size_t)inst*NPAD*KPAD + (size_t)n*KPAD + k] = __float2bfloat16(src[(size_t)k*DIM + n]);
}

// ================= HMMA machinery (R4 geometry) ============================
struct MmaCtx {
    int aAtom0, aAtom1, aLine0, aLine1, aKadd;
    int bAtom0, bAtom1, bLine0, bLine1, bKadd;
};
__device__ __forceinline__ void mma_setup(MmaCtx& cx, int tid) {
    int lane = tid & 31, i = lane >> 3, rr = lane & 7;
    int w = tid >> 5;
    int wm = w >> 1, wn = w & 1;
    int ar0 = wm*32 + (i&1)*8 + rr;
    int ar1 = ar0 + 16;
    int br0 = wn*32 + (i>>1)*8 + rr;
    int br1 = br0 + 16;
    cx.aAtom0 = (ar0>>3)*1024; cx.aLine0 = (ar0&7)*128;
    cx.aAtom1 = (ar1>>3)*1024; cx.aLine1 = (ar1&7)*128;
    cx.aKadd = (i>>1)*16;
    cx.bAtom0 = (br0>>3)*1024; cx.bLine0 = (br0&7)*128;
    cx.bAtom1 = (br1>>3)*1024; cx.bLine1 = (br1&7)*128;
    cx.bKadd = (i&1)*16;
}
__device__ __forceinline__ void mma_chunk(const MmaCtx& cx, uint32_t aA, uint32_t aB,
                                          float acc[2][4][4]) {
    #pragma unroll
    for (int ks = 0; ks < 4; ks++) {
        int kb = ks*32;
        uint32_t a0[4], a1[4], b0[4], b1[4];
        ldmx4(a0, aA + cx.aAtom0 + SW128(cx.aLine0 + kb + cx.aKadd));
        ldmx4(a1, aA + cx.aAtom1 + SW128(cx.aLine1 + kb + cx.aKadd));
        ldmx4(b0, aB + cx.bAtom0 + SW128(cx.bLine0 + kb + cx.bKadd));
        ldmx4(b1, aB + cx.bAtom1 + SW128(cx.bLine1 + kb + cx.bKadd));
        mma16816(acc[0][0], a0, b0);
        mma16816(acc[0][1], a0, b0 + 2);
        mma16816(acc[0][2], a0, b1);
        mma16816(acc[0][3], a0, b1 + 2);
        mma16816(acc[1][0], a1, b0);
        mma16816(acc[1][1], a1, b0 + 2);
        mma16816(acc[1][2], a1, b1);
        mma16816(acc[1][3], a1, b1 + 2);
    }
}
__device__ __forceinline__ void load_a128_async(uint32_t sA, const __nv_bfloat16* Ag,
                                                int row0, int rmax, int c, int tid) {
    #pragma unroll
    for (int i = 0; i < 4; i++) {
        int idx = tid + i*256;
        int r = idx >> 3, q = idx & 7;
        int gr = row0 + r; if (gr >= rmax) gr = 0;
        uint32_t off = (uint32_t)((r>>3)*1024) + SW128((uint32_t)((r&7)*128 + q*16));
        cpa16(sA + off, Ag + (size_t)gr*KPAD + c*64 + q*8);
    }
}
__device__ __forceinline__ void load_b64_async(uint32_t sB, const __nv_bfloat16* Bg,
                                               int row0, int rmax, int c, int tid) {
    #pragma unroll
    for (int i = 0; i < 2; i++) {
        int idx = tid + i*256;
        int r = idx >> 3, q = idx & 7;
        int gr = row0 + r; if (gr >= rmax) gr = 0;
        uint32_t off = (uint32_t)((r>>3)*1024) + SW128((uint32_t)((r&7)*128 + q*16));
        cpa16(sB + off, Bg + (size_t)gr*KPAD + c*64 + q*8);
    }
}

// ================= GEMM 1: e0 @ W; split by inst0 (UV vs node halves) ======
__global__ void __launch_bounds__(256) mm_e0w_k(
    const float* __restrict__ nb1, const float* __restrict__ eb1,
    const float* __restrict__ nW2, int inst0)
{
    __shared__ __align__(1024) uint8_t sA[2][16384];
    __shared__ __align__(1024) uint8_t sB[2][8192];
    int bm = blockIdx.x, nt64 = blockIdx.y, inst = inst0 + blockIdx.z;
    int tid = threadIdx.x;
    uint32_t aA0 = smem_u32(sA[0]), aA1 = smem_u32(sA[1]);
    uint32_t aB0 = smem_u32(sB[0]), aB1 = smem_u32(sB[1]);

    MmaCtx cx; mma_setup(cx, tid);
    float acc[2][4][4];
    #pragma unroll
    for (int a = 0; a < 2; a++)
        #pragma unroll
        for (int b = 0; b < 4; b++)
            #pragma unroll
            for (int q = 0; q < 4; q++) acc[a][b][q] = 0.f;

    const __nv_bfloat16* Bg = g_Wtb + (size_t)inst*NPAD*KPAD;

    load_a128_async(aA0, g_e0b, bm*128, NE, 0, tid);
    load_b64_async (aB0, Bg, nt64*64, NPAD, 0, tid);
    CPA_COMMIT();
    #pragma unroll
    for (int c = 0; c < NCHUNK; c++) {
        uint32_t curA = (c & 1) ? aA1 : aA0, curB = (c & 1) ? aB1 : aB0;
        if (c + 1 < NCHUNK) {
            uint32_t nxtA = ((c+1) & 1) ? aA1 : aA0, nxtB = ((c+1) & 1) ? aB1 : aB0;
            load_a128_async(nxtA, g_e0b, bm*128, NE, c+1, tid);
            load_b64_async (nxtB, Bg, nt64*64, NPAD, c+1, tid);
            CPA_COMMIT();
            CPA_WAIT(1);
        } else {
            CPA_WAIT(0);
        }
        __syncthreads();
        mma_chunk(cx, curA, curB, acc);
        __syncthreads();
    }

    int lane = tid & 31, w = tid >> 5;
    int wm = w >> 1, wn = w & 1;
    int mrow = lane >> 2, ncol = (lane & 3)*2;
    int nbase = nt64*64 + wn*32;

    if (inst < 2) {
        const float* bias = nb1 + inst*DIM;
        const float* W2 = nW2 + inst*DIM;
        int seg = nt64*2 + wn;
        #pragma unroll
        for (int mt = 0; mt < 2; mt++) {
            float p0 = 0.f, p1 = 0.f;
            #pragma unroll
            for (int nt = 0; nt < 4; nt++) {
                int n = nbase + nt*8 + ncol;
                float b0 = 0.f, b1v = 0.f, w0 = 0.f, w1 = 0.f;
                if (n < DIM)     { b0 = bias[n];   w0 = W2[n];   }
                if (n + 1 < DIM) { b1v = bias[n+1]; w1 = W2[n+1]; }
                p0 = fmaf(fmaxf(acc[mt][nt][0] + b0, 0.f), w0, p0);
                p0 = fmaf(fmaxf(acc[mt][nt][1] + b1v, 0.f), w1, p0);
                p1 = fmaf(fmaxf(acc[mt][nt][2] + b0, 0.f), w0, p1);
                p1 = fmaf(fmaxf(acc[mt][nt][3] + b1v, 0.f), w1, p1);
            }
            p0 += __shfl_xor_sync(0xffffffffu, p0, 1);
            p0 += __shfl_xor_sync(0xffffffffu, p0, 2);
            p1 += __shfl_xor_sync(0xffffffffu, p1, 1);
            p1 += __shfl_xor_sync(0xffffffffu, p1, 2);
            if ((lane & 3) == 0) {
                int m0 = bm*128 + wm*32 + mt*16 + mrow;
                if (m0 < NE)     g_PL[((size_t)inst*NE + m0)*8 + seg] = p0;
                if (m0 + 8 < NE) g_PL[((size_t)inst*NE + m0 + 8)*8 + seg] = p1;
            }
        }
    } else {
        __nv_bfloat16* C = (inst == 2) ? g_Ub : g_Vb;
        const float* bias = (inst == 3) ? (eb1 + DIM) : nullptr;
        #pragma unroll
        for (int mt = 0; mt < 2; mt++) {
            int m = bm*128 + wm*32 + mt*16 + mrow;
            if (m >= NE) continue;
            #pragma unroll
            for (int nt = 0; nt < 4; nt++) {
                int n = nbase + nt*8 + ncol;
                if (n >= DIM) continue;
                float b0 = bias ? bias[n] : 0.f, b1 = bias ? bias[n+1] : 0.f;
                __nv_bfloat162 p, q;
                p.x = __float2bfloat16(acc[mt][nt][0] + b0);
                p.y = __float2bfloat16(acc[mt][nt][1] + b1);
                q.x = __float2bfloat16(acc[mt][nt][2] + b0);
                q.y = __float2bfloat16(acc[mt][nt][3] + b1);
                *(__nv_bfloat162*)(C + (size_t)m*DIM + n) = p;
                if (m + 8 < NE) *(__nv_bfloat162*)(C + (size_t)(m+8)*DIM + n) = q;
            }
        }
    }
}

// gate finalize
__global__ void gate_fin_k(const float* __restrict__ nb2, const float* __restrict__ eps,
                           float* __restrict__ mask) {
    int idx = blockIdx.x*blockDim.x + threadIdx.x;
    if (idx >= 2*NE) return;
    int inst = idx / NE;
    const float* p = g_PL + (size_t)idx*8;
    float4 a = *(const float4*)p;
    float4 b = *(const float4*)(p + 4);
    float s = ((a.x + a.y) + (a.z + a.w)) + ((b.x + b.y) + (b.z + b.w));
    mask[idx] = gate_fn(s + nb2[inst], eps[idx]);
}

// ================= GEMM 2: scores ==========================================
__global__ void __launch_bounds__(256) scores_mm_k(float* __restrict__ out)
{
    __shared__ __align__(1024) uint8_t sA[2][16384];
    __shared__ __align__(1024) uint8_t sB[2][8192];
    int bx = blockIdx.x, by = blockIdx.y;
    int tid = threadIdx.x;
    uint32_t aA0 = smem_u32(sA[0]), aA1 = smem_u32(sA[1]);
    uint32_t aB0 = smem_u32(sB[0]), aB1 = smem_u32(sB[1]);

    MmaCtx cx; mma_setup(cx, tid);
    float acc[2][4][4];
    #pragma unroll
    for (int a = 0; a < 2; a++)
        #pragma unroll
        for (int b = 0; b < 4; b++)
            #pragma unroll
            for (int q = 0; q < 4; q++) acc[a][b][q] = 0.f;

    load_a128_async(aA0, g_hrb, by*128, BATCH, 0, tid);
    load_b64_async (aB0, g_e0b, bx*64, NE, 0, tid);
    CPA_COMMIT();
    #pragma unroll
    for (int c = 0; c < NCHUNK; c++) {
        uint32_t curA = (c & 1) ? aA1 : aA0, curB = (c & 1) ? aB1 : aB0;
        if (c + 1 < NCHUNK) {
            uint32_t nxtA = ((c+1) & 1) ? aA1 : aA0, nxtB = ((c+1) & 1) ? aB1 : aB0;
            load_a128_async(nxtA, g_hrb, by*128, BATCH, c+1, tid);
            load_b64_async (nxtB, g_e0b, bx*64, NE, c+1, tid);
            CPA_COMMIT();
            CPA_WAIT(1);
        } else {
            CPA_WAIT(0);
        }
        __syncthreads();
        mma_chunk(cx, curA, curB, acc);
        __syncthreads();
    }

    int lane = tid & 31, w = tid >> 5;
    int wm = w >> 1, wn = w & 1;
    int mrow = lane >> 2, ncol = (lane & 3)*2;
    #pragma unroll
    for (int mt = 0; mt < 2; mt++) {
        int m = by*128 + wm*32 + mt*16 + mrow;
        #pragma unroll
        for (int nt = 0; nt < 4; nt++) {
            int n = bx*64 + wn*32 + nt*8 + ncol;
            if (n < NE) {
                float2 v01, v23;
                v01.x = 1.f/(1.f + __expf(-acc[mt][nt][0]));
                v01.y = 1.f/(1.f + __expf(-acc[mt][nt][1]));
                v23.x = 1.f/(1.f + __expf(-acc[mt][nt][2]));
                v23.y = 1.f/(1.f + __expf(-acc[mt][nt][3]));
                *(float2*)(out + (size_t)m*NE + n) = v01;
                *(float2*)(out + (size_t)(m+8)*NE + n) = v23;
            }
        }
    }
}

// ================= support kernels =================
__global__ void rowptr_k(const int* __restrict__ row, int nnz, int* __restrict__ rowptr) {
    int n = blockIdx.x*blockDim.x + threadIdx.x;
    if (n > NE) return;
    int lo = 0, hi = nnz;
    while (lo < hi) { int mid = (lo+hi) >> 1; if (row[mid] < n) lo = mid+1; else hi = mid; }
    rowptr[n] = lo;
}

// edge gate: warp per ROW; U row + W2 cached in registers, only V gathered
__global__ void edge_gate_row_k(const int* __restrict__ rowptr, const int* __restrict__ col,
                                const float* __restrict__ adj_val,
                                const float* __restrict__ W2, const float* __restrict__ b2,
                                const float* __restrict__ eps, float* __restrict__ new_edge) {
    int r = (blockIdx.x*blockDim.x + threadIdx.x) >> 5;
    int lane = threadIdx.x & 31;
    if (r >= NE) return;
    int s = rowptr[r], e = rowptr[r+1];
    if (s >= e) return;

    uint4 uu = {0,0,0,0};
    float4 w01 = {0,0,0,0}, w23 = {0,0,0,0};
    if (lane < 25) {
        uu  = __ldg((const uint4*)(g_Ub + (size_t)r*DIM) + lane);
        w01 = __ldg((const float4*)(W2 + lane*8));
        w23 = __ldg((const float4*)(W2 + lane*8 + 4));
    }
    float b2v = b2[0];

    for (int idx = s; idx < e; idx++) {
        int c = __ldg(&col[idx]);
        float acc = 0.f;
        if (lane < 25) {
            uint4 vv = __ldg((const uint4*)(g_Vb + (size_t)c*DIM) + lane);
            const __nv_bfloat162* up = (const __nv_bfloat162*)&uu;
            const __nv_bfloat162* vp = (const __nv_bfloat162*)&vv;
            const float* wp = (const float*)&w01;
            const float* wq = (const float*)&w23;
            #pragma unroll
            for (int t = 0; t < 2; t++) {
                __nv_bfloat162 a = up[t], b = vp[t];
                float h0 = fmaxf(__bfloat162float(a.x) + __bfloat162float(b.x), 0.f);
                float h1 = fmaxf(__bfloat162float(a.y) + __bfloat162float(b.y), 0.f);
                acc = fmaf(h0, wp[2*t], acc);
                acc = fmaf(h1, wp[2*t+1], acc);
            }
            #pragma unroll
            for (int t = 0; t < 2; t++) {
                __nv_bfloat162 a = up[2+t], b = vp[2+t];
                float h0 = fmaxf(__bfloat162float(a.x) + __bfloat162float(b.x), 0.f);
                float h1 = fmaxf(__bfloat162float(a.y) + __bfloat162float(b.y), 0.f);
                acc = fmaf(h0, wq[2*t], acc);
                acc = fmaf(h1, wq[2*t+1], acc);
            }
        }
        acc = warp_sum(acc);
        if (lane == 0)
            new_edge[idx] = __ldg(&adj_val[idx]) * gate_fn(acc + b2v, __ldg(&eps[idx]));
    }
}

// plain CSR SpMM (R9 scalar — measured best)
__global__ void spmm_k(const int* __restrict__ rowptr, const int* __restrict__ col,
                       const float* __restrict__ val, const float* __restrict__ x,
                       float* __restrict__ y) {
    int r = (blockIdx.x*blockDim.x + threadIdx.x) >> 5;
    int lane = threadIdx.x & 31;
    if (r >= NE) return;
    float acc[7];
    #pragma unroll
    for (int u = 0; u < 7; u++) acc[u] = 0.f;
    int s = rowptr[r], e = rowptr[r+1];
    for (int idx = s; idx < e; idx++) {
        int c = __ldg(&col[idx]);
        float v = __ldg(&val[idx]);
        const float* xr = x + (size_t)c*DIM;
        #pragma unroll
        for (int u = 0; u < 7; u++) {
            int j = lane + 32*u;
            if (j < 200) acc[u] = fmaf(v, xr[j], acc[u]);
        }
    }
    float* yr = y + (size_t)r*DIM;
    #pragma unroll
    for (int u = 0; u < 7; u++) {
        int j = lane + 32*u;
        if (j < 200) yr[j] = acc[u];
    }
}

__global__ void spmm_mix_k(const int* __restrict__ rowptr, const int* __restrict__ col,
                           const float* __restrict__ val, const float* __restrict__ x,
                           const float* __restrict__ mask, float* __restrict__ y) {
    int r = (blockIdx.x*blockDim.x + threadIdx.x) >> 5;
    int lane = threadIdx.x & 31;
    if (r >= NE) return;
    float acc[7];
    #pragma unroll
    for (int u = 0; u < 7; u++) acc[u] = 0.f;
    int s = rowptr[r], e = rowptr[r+1];
    for (int idx = s; idx < e; idx++) {
        int c = __ldg(&col[idx]);
        float v = __ldg(&val[idx]);
        const float* xr = x + (size_t)c*DIM;
        #pragma unroll
        for (int u = 0; u < 7; u++) {
            int j = lane + 32*u;
            if (j < 200) acc[u] = fmaf(v, xr[j], acc[u]);
        }
    }
    float m = mask[r];
    const float* xr = x + (size_t)r*DIM;
    float* yr = y + (size_t)r*DIM;
    #pragma unroll
    for (int u = 0; u < 7; u++) {
        int j = lane + 32*u;
        if (j < 200) yr[j] = m*xr[j] + (1.f - m)*acc[u];
    }
}

__global__ void mix_k(const float* __restrict__ x, const float* __restrict__ mp,
                      const float* __restrict__ mask, float* __restrict__ y) {
    int idx = blockIdx.x*blockDim.x + threadIdx.x;
    if (idx >= NE*DIM) return;
    float m = mask[idx / DIM];
    y[idx] = m*x[idx] + (1.f - m)*mp[idx];
}

// RESCAL -> bf16 hrb
__global__ void rescal_k(const float* __restrict__ e0, const float* __restrict__ rel_emb,
                         const int* __restrict__ sub, const int* __restrict__ rel) {
    int b = blockIdx.x;
    int j = threadIdx.x;
    __shared__ float ls[DIM];
    const float* lhs = e0 + (size_t)sub[b]*DIM;
    if (j < DIM) ls[j] = lhs[j];
    __syncthreads();
    if (j < DIM) {
        const float* R = rel_emb + (size_t)rel[b]*RELD;
        float acc = 0.f;
        #pragma unroll 4
        for (int k = 0; k < DIM; k++) acc = fmaf(ls[k], R[(size_t)k*DIM + j], acc);
        g_hrb[(size_t)b*KPAD + j] = __float2bfloat16(acc);
    }
}

// ================= launch ==================================================
extern "C" void kernel_launch(void* const* d_in, const int* in_sizes, int n_in,
                              void* d_out, int out_size) {
    const float* e0       = (const float*)d_in[0];
    const float* rel_emb  = (const float*)d_in[1];
    const float* nW1      = (const float*)d_in[2];
    const float* nb1      = (const float*)d_in[3];
    const float* nW2      = (const float*)d_in[4];
    const float* nb2      = (const float*)d_in[5];
    const float* eW1      = (const float*)d_in[6];
    const float* eb1      = (const float*)d_in[7];
    const float* eW2      = (const float*)d_in[8];
    const float* eb2      = (const float*)d_in[9];
    const int*   adj_row  = (const int*)d_in[10];
    const int*   adj_col  = (const int*)d_in[11];
    const float* adj_val  = (const float*)d_in[12];
    const int*   rw_row   = (const int*)d_in[13];
    const int*   rw_col   = (const int*)d_in[14];
    const float* rw_val   = (const float*)d_in[15];
    const float* node_eps = (const float*)d_in[16];
    const float* edge_eps = (const float*)d_in[17];
    const int*   sub      = (const int*)d_in[18];
    const int*   rel      = (const int*)d_in[19];

    int E   = in_sizes[10];
    int Erw = in_sizes[13];

    float* out        = (float*)d_out;
    float* out_scores = out;
    float* out_xnd    = out + (size_t)BATCH*NE;
    float* out_xed    = out_xnd + (size_t)NE*DIM;

    float *X1, *X2, *MP, *E2, *NMASK, *NEWEDGE;
    int *RPA, *RPR;
    cudaGetSymbolAddress((void**)&X1, g_X1);
    cudaGetSymbolAddress((void**)&X2, g_X2);
    cudaGetSymbolAddress((void**)&MP, g_MP);
    cudaGetSymbolAddress((void**)&E2, g_E2);
    cudaGetSymbolAddress((void**)&NMASK, g_NMASK);
    cudaGetSymbolAddress((void**)&NEWEDGE, g_NEWEDGE);
    cudaGetSymbolAddress((void**)&RPA, g_rp_adj);
    cudaGetSymbolAddress((void**)&RPR, g_rp_rw);

    static cudaStream_t s1 = nullptr, s2 = nullptr;
    static cudaEvent_t evFork0, evConv, evRw, evUV, evMP, evS1, evS2;
    if (!s1) {
        cudaStreamCreateWithFlags(&s1, cudaStreamNonBlocking);
        cudaStreamCreateWithFlags(&s2, cudaStreamNonBlocking);
        cudaEventCreateWithFlags(&evFork0, cudaEventDisableTiming);
        cudaEventCreateWithFlags(&evConv,  cudaEventDisableTiming);
        cudaEventCreateWithFlags(&evRw,    cudaEventDisableTiming);
        cudaEventCreateWithFlags(&evUV,    cudaEventDisableTiming);
        cudaEventCreateWithFlags(&evMP,    cudaEventDisableTiming);
        cudaEventCreateWithFlags(&evS1,    cudaEventDisableTiming);
        cudaEventCreateWithFlags(&evS2,    cudaEventDisableTiming);
    }

    const int SPB = (NE*32 + 255)/256;
    const int MT  = (NE + 127)/128;

    // ---- fork point ----
    cudaEventRecord(evFork0, 0);

    // ---- main stream: prep ----
    rowptr_k<<<(NE+1+255)/256, 256>>>(rw_row, Erw, RPR);
    cudaEventRecord(evRw, 0);
    rowptr_k<<<(NE+1+255)/256, 256>>>(adj_row, E, RPA);
    conv_e0_k<<<(NE*50 + 255)/256, 256>>>(e0);
    cudaEventRecord(evConv, 0);
    dim3 wgrid((DIM*DIM + 255)/256, 4);
    conv_w_k<<<wgrid, 256>>>(nW1, eW1);

    // ---- s1: rescal -> scores ----
    cudaStreamWaitEvent(s1, evFork0, 0);
    rescal_k<<<BATCH, 256, 0, s1>>>(e0, rel_emb, sub, rel);
    cudaStreamWaitEvent(s1, evConv, 0);
    dim3 sgrid((NE + 63)/64, BATCH/128);
    scores_mm_k<<<sgrid, 256, 0, s1>>>(out_scores);
    cudaEventRecord(evS1, s1);

    // ---- s2: edge-branch rw propagation ----
    cudaStreamWaitEvent(s2, evRw, 0);
    spmm_k<<<SPB, 256, 0, s2>>>(RPR, rw_col, rw_val, e0, MP);
    cudaEventRecord(evMP, s2);
    spmm_k<<<SPB, 256, 0, s2>>>(RPR, rw_col, rw_val, MP, E2);

    // ---- main: UV half of GEMM first (unblocks edge gate early) ----
    dim3 mgrid(MT, 4, 2);
    mm_e0w_k<<<mgrid, 256>>>(nb1, eb1, nW2, 2);   // inst 2,3 -> U,V
    cudaEventRecord(evUV, 0);
    mm_e0w_k<<<mgrid, 256>>>(nb1, eb1, nW2, 0);   // inst 0,1 -> node dots
    gate_fin_k<<<(2*NE + 255)/256, 256>>>(nb2, node_eps, NMASK);

    // ---- s2: edge gate (row-warp, cached U) + final edge spmm ----
    cudaStreamWaitEvent(s2, evUV, 0);
    edge_gate_row_k<<<SPB, 256, 0, s2>>>(RPA, adj_col, adj_val,
                                         eW2 + DIM, eb2 + 1, edge_eps + E, NEWEDGE);
    spmm_k<<<SPB, 256, 0, s2>>>(RPA, adj_col, NEWEDGE, E2, out_xed);
    cudaEventRecord(evS2, s2);

    // ---- main: node-drop branch ----
    cudaStreamWaitEvent(0, evMP, 0);
    mix_k<<<(NE*DIM + 255)/256, 256>>>(e0, MP, NMASK, X1);
    spmm_k<<<SPB, 256>>>(RPA, adj_col, adj_val, X1, X2);
    spmm_mix_k<<<SPB, 256>>>(RPR, rw_col, rw_val, X2, NMASK + NE, X1);
    spmm_k<<<SPB, 256>>>(RPA, adj_col, adj_val, X1, out_xnd);

    // ---- join ----
    cudaStreamWaitEvent(0, evS1, 0);
    cudaStreamWaitEvent(0, evS2, 0);
}

// round 14
// speedup vs baseline: 1.0853x; 1.0629x over previous
#include <cuda_runtime.h>
#include <cuda_bf16.h>
#include <cuda_fp16.h>
#include <math.h>
#include <stdint.h>

#define NE    50000
#define DIM   200
#define BATCH 1024
#define EMAX  400000
#define RELD  40000
#define KPAD  256
#define NCHUNK 4
#define NPAD  256

// ---------------- scratch (zero-init => pad regions stay 0)
__device__ __align__(16) __nv_bfloat16 g_e0b[(size_t)NE*KPAD];
__device__ __align__(16) __nv_bfloat16 g_hrb[(size_t)BATCH*KPAD];
__device__ __align__(16) __nv_bfloat16 g_Wtb[(size_t)4*NPAD*KPAD];
__device__ __align__(16) __nv_bfloat16 g_Ub[(size_t)NE*DIM];
__device__ __align__(16) __nv_bfloat16 g_Vb[(size_t)NE*DIM];
__device__ __align__(16) float g_PL[(size_t)2*NE*8];
__device__ __align__(16) __half g_e0h[(size_t)NE*DIM];   // fp16 e0 for propagation
__device__ __align__(16) __half g_X1h[(size_t)NE*DIM];
__device__ __align__(16) __half g_X2h[(size_t)NE*DIM];
__device__ __align__(16) __half g_MPh[(size_t)NE*DIM];
__device__ __align__(16) __half g_E2h[(size_t)NE*DIM];
__device__ float g_NMASK[2*NE];
__device__ float g_NEWEDGE[EMAX];
__device__ int   g_rp_adj[NE+1];
__device__ int   g_rp_rw [NE+1];

// ================= helpers =================
__device__ __forceinline__ uint32_t smem_u32(const void* p) {
    uint32_t a;
    asm("{ .reg .u64 t; cvta.to.shared.u64 t, %1; cvt.u32.u64 %0, t; }" : "=r"(a) : "l"(p));
    return a;
}
#define SW128(o) ((o) ^ (((o) >> 3) & 0x70))

__device__ __forceinline__ void ldmx4(uint32_t* r, uint32_t addr) {
    asm volatile("ldmatrix.sync.aligned.m8n8.x4.shared.b16 {%0,%1,%2,%3}, [%4];"
        : "=r"(r[0]), "=r"(r[1]), "=r"(r[2]), "=r"(r[3]) : "r"(addr));
}
__device__ __forceinline__ void mma16816(float* c, const uint32_t* a, const uint32_t* b) {
    asm volatile("mma.sync.aligned.m16n8k16.row.col.f32.bf16.bf16.f32 "
        "{%0,%1,%2,%3}, {%4,%5,%6,%7}, {%8,%9}, {%0,%1,%2,%3};"
        : "+f"(c[0]), "+f"(c[1]), "+f"(c[2]), "+f"(c[3])
        : "r"(a[0]), "r"(a[1]), "r"(a[2]), "r"(a[3]), "r"(b[0]), "r"(b[1]));
}
__device__ __forceinline__ void cpa16(uint32_t dst, const void* src) {
    asm volatile("cp.async.cg.shared.global [%0], [%1], 16;" :: "r"(dst), "l"(src));
}
#define CPA_COMMIT() asm volatile("cp.async.commit_group;" ::: "memory")
#define CPA_WAIT(n)  asm volatile("cp.async.wait_group %0;" :: "n"(n) : "memory")

__device__ __forceinline__ float gate_fn(float logits, float u) {
    const float bias = 1e-4f;
    float eps = (2.f*bias - 1.f)*u + (1.f - bias);
    float t = 2.f*(__logf(eps) - __logf(1.f - eps) + logits);
    return 1.f/(1.f + __expf(-t));
}
__device__ __forceinline__ float warp_sum(float v) {
    #pragma unroll
    for (int o = 16; o; o >>= 1) v += __shfl_xor_sync(0xffffffffu, v, o);
    return v;
}

// ================= conversion kernels =================
__global__ void conv_e0_k(const float* __restrict__ e0) {
    int t = blockIdx.x*blockDim.x + threadIdx.x;
    if (t >= NE*50) return;
    int row = t/50, k = (t%50)*4;
    float4 v = *(const float4*)(e0 + (size_t)row*DIM + k);
    __nv_bfloat162 p0, p1;
    p0.x = __float2bfloat16(v.x); p0.y = __float2bfloat16(v.y);
    p1.x = __float2bfloat16(v.z); p1.y = __float2bfloat16(v.w);
    __nv_bfloat16* d = g_e0b + (size_t)row*KPAD + k;
    *(__nv_bfloat162*)(d)     = p0;
    *(__nv_bfloat162*)(d + 2) = p1;
    // fp16 copy for the SpMM chain
    __half2 h0 = __floats2half2_rn(v.x, v.y);
    __half2 h1 = __floats2half2_rn(v.z, v.w);
    __half* dh = g_e0h + (size_t)row*DIM + k;
    *(__half2*)(dh)     = h0;
    *(__half2*)(dh + 2) = h1;
}

__global__ void conv_w_k(const float* __restrict__ nW1, const float* __restrict__ eW1) {
    int inst = blockIdx.y;
    int t = blockIdx.x*blockDim.x + threadIdx.x;
    if (t >= DIM*DIM) return;
    const float* src;
    if (inst == 0)      src = nW1;
    else if (inst == 1) src = nW1 + RELD;
    else if (inst == 2) src = eW1 + 2*RELD;
    else                src = eW1 + 3*RELD;
    int n = t/DIM, k = t%DIM;
    g_Wtb[(size_t)inst*NPAD*KPAD + (size_t)n*KPAD + k] = __float2bfloat16(src[(size_t)k*DIM + n]);
}

// ================= HMMA machinery (R4 geometry) ============================
struct MmaCtx {
    int aAtom0, aAtom1, aLine0, aLine1, aKadd;
    int bAtom0, bAtom1, bLine0, bLine1, bKadd;
};
__device__ __forceinline__ void mma_setup(MmaCtx& cx, int tid) {
    int lane = tid & 31, i = lane >> 3, rr = lane & 7;
    int w = tid >> 5;
    int wm = w >> 1, wn = w & 1;
    int ar0 = wm*32 + (i&1)*8 + rr;
    int ar1 = ar0 + 16;
    int br0 = wn*32 + (i>>1)*8 + rr;
    int br1 = br0 + 16;
    cx.aAtom0 = (ar0>>3)*1024; cx.aLine0 = (ar0&7)*128;
    cx.aAtom1 = (ar1>>3)*1024; cx.aLine1 = (ar1&7)*128;
    cx.aKadd = (i>>1)*16;
    cx.bAtom0 = (br0>>3)*1024; cx.bLine0 = (br0&7)*128;
    cx.bAtom1 = (br1>>3)*1024; cx.bLine1 = (br1&7)*128;
    cx.bKadd = (i&1)*16;
}
__device__ __forceinline__ void mma_chunk(const MmaCtx& cx, uint32_t aA, uint32_t aB,
                                          float acc[2][4][4]) {
    #pragma unroll
    for (int ks = 0; ks < 4; ks++) {
        int kb = ks*32;
        uint32_t a0[4], a1[4], b0[4], b1[4];
        ldmx4(a0, aA + cx.aAtom0 + SW128(cx.aLine0 + kb + cx.aKadd));
        ldmx4(a1, aA + cx.aAtom1 + SW128(cx.aLine1 + kb + cx.aKadd));
        ldmx4(b0, aB + cx.bAtom0 + SW128(cx.bLine0 + kb + cx.bKadd));
        ldmx4(b1, aB + cx.bAtom1 + SW128(cx.bLine1 + kb + cx.bKadd));
        mma16816(acc[0][0], a0, b0);
        mma16816(acc[0][1], a0, b0 + 2);
        mma16816(acc[0][2], a0, b1);
        mma16816(acc[0][3], a0, b1 + 2);
        mma16816(acc[1][0], a1, b0);
        mma16816(acc[1][1], a1, b0 + 2);
        mma16816(acc[1][2], a1, b1);
        mma16816(acc[1][3], a1, b1 + 2);
    }
}
__device__ __forceinline__ void load_a128_async(uint32_t sA, const __nv_bfloat16* Ag,
                                                int row0, int rmax, int c, int tid) {
    #pragma unroll
    for (int i = 0; i < 4; i++) {
        int idx = tid + i*256;
        int r = idx >> 3, q = idx & 7;
        int gr = row0 + r; if (gr >= rmax) gr = 0;
        uint32_t off = (uint32_t)((r>>3)*1024) + SW128((uint32_t)((r&7)*128 + q*16));
        cpa16(sA + off, Ag + (size_t)gr*KPAD + c*64 + q*8);
    }
}
__device__ __forceinline__ void load_b64_async(uint32_t sB, const __nv_bfloat16* Bg,
                                               int row0, int rmax, int c, int tid) {
    #pragma unroll
    for (int i = 0; i < 2; i++) {
        int idx = tid + i*256;
        int r = idx >> 3, q = idx & 7;
        int gr = row0 + r; if (gr >= rmax) gr = 0;
        uint32_t off = (uint32_t)((r>>3)*1024) + SW128((uint32_t)((r&7)*128 + q*16));
        cpa16(sB + off, Bg + (size_t)gr*KPAD + c*64 + q*8);
    }
}

// ================= GEMM 1: e0 @ W; split by inst0 ==========================
__global__ void __launch_bounds__(256) mm_e0w_k(
    const float* __restrict__ nb1, const float* __restrict__ eb1,
    const float* __restrict__ nW2, int inst0)
{
    __shared__ __align__(1024) uint8_t sA[2][16384];
    __shared__ __align__(1024) uint8_t sB[2][8192];
    int bm = blockIdx.x, nt64 = blockIdx.y, inst = inst0 + blockIdx.z;
    int tid = threadIdx.x;
    uint32_t aA0 = smem_u32(sA[0]), aA1 = smem_u32(sA[1]);
    uint32_t aB0 = smem_u32(sB[0]), aB1 = smem_u32(sB[1]);

    MmaCtx cx; mma_setup(cx, tid);
    float acc[2][4][4];
    #pragma unroll
    for (int a = 0; a < 2; a++)
        #pragma unroll
        for (int b = 0; b < 4; b++)
            #pragma unroll
            for (int q = 0; q < 4; q++) acc[a][b][q] = 0.f;

    const __nv_bfloat16* Bg = g_Wtb + (size_t)inst*NPAD*KPAD;

    load_a128_async(aA0, g_e0b, bm*128, NE, 0, tid);
    load_b64_async (aB0, Bg, nt64*64, NPAD, 0, tid);
    CPA_COMMIT();
    #pragma unroll
    for (int c = 0; c < NCHUNK; c++) {
        uint32_t curA = (c & 1) ? aA1 : aA0, curB = (c & 1) ? aB1 : aB0;
        if (c + 1 < NCHUNK) {
            uint32_t nxtA = ((c+1) & 1) ? aA1 : aA0, nxtB = ((c+1) & 1) ? aB1 : aB0;
            load_a128_async(nxtA, g_e0b, bm*128, NE, c+1, tid);
            load_b64_async (nxtB, Bg, nt64*64, NPAD, c+1, tid);
            CPA_COMMIT();
            CPA_WAIT(1);
        } else {
            CPA_WAIT(0);
        }
        __syncthreads();
        mma_chunk(cx, curA, curB, acc);
        __syncthreads();
    }

    int lane = tid & 31, w = tid >> 5;
    int wm = w >> 1, wn = w & 1;
    int mrow = lane >> 2, ncol = (lane & 3)*2;
    int nbase = nt64*64 + wn*32;

    if (inst < 2) {
        const float* bias = nb1 + inst*DIM;
        const float* W2 = nW2 + inst*DIM;
        int seg = nt64*2 + wn;
        #pragma unroll
        for (int mt = 0; mt < 2; mt++) {
            float p0 = 0.f, p1 = 0.f;
            #pragma unroll
            for (int nt = 0; nt < 4; nt++) {
                int n = nbase + nt*8 + ncol;
                float b0 = 0.f, b1v = 0.f, w0 = 0.f, w1 = 0.f;
                if (n < DIM)     { b0 = bias[n];   w0 = W2[n];   }
                if (n + 1 < DIM) { b1v = bias[n+1]; w1 = W2[n+1]; }
                p0 = fmaf(fmaxf(acc[mt][nt][0] + b0, 0.f), w0, p0);
                p0 = fmaf(fmaxf(acc[mt][nt][1] + b1v, 0.f), w1, p0);
                p1 = fmaf(fmaxf(acc[mt][nt][2] + b0, 0.f), w0, p1);
                p1 = fmaf(fmaxf(acc[mt][nt][3] + b1v, 0.f), w1, p1);
            }
            p0 += __shfl_xor_sync(0xffffffffu, p0, 1);
            p0 += __shfl_xor_sync(0xffffffffu, p0, 2);
            p1 += __shfl_xor_sync(0xffffffffu, p1, 1);
            p1 += __shfl_xor_sync(0xffffffffu, p1, 2);
            if ((lane & 3) == 0) {
                int m0 = bm*128 + wm*32 + mt*16 + mrow;
                if (m0 < NE)     g_PL[((size_t)inst*NE + m0)*8 + seg] = p0;
                if (m0 + 8 < NE) g_PL[((size_t)inst*NE + m0 + 8)*8 + seg] = p1;
            }
        }
    } else {
        __nv_bfloat16* C = (inst == 2) ? g_Ub : g_Vb;
        const float* bias = (inst == 3) ? (eb1 + DIM) : nullptr;
        #pragma unroll
        for (int mt = 0; mt < 2; mt++) {
            int m = bm*128 + wm*32 + mt*16 + mrow;
            if (m >= NE) continue;
            #pragma unroll
            for (int nt = 0; nt < 4; nt++) {
                int n = nbase + nt*8 + ncol;
                if (n >= DIM) continue;
                float b0 = bias ? bias[n] : 0.f, b1 = bias ? bias[n+1] : 0.f;
                __nv_bfloat162 p, q;
                p.x = __float2bfloat16(acc[mt][nt][0] + b0);
                p.y = __float2bfloat16(acc[mt][nt][1] + b1);
                q.x = __float2bfloat16(acc[mt][nt][2] + b0);
                q.y = __float2bfloat16(acc[mt][nt][3] + b1);
                *(__nv_bfloat162*)(C + (size_t)m*DIM + n) = p;
                if (m + 8 < NE) *(__nv_bfloat162*)(C + (size_t)(m+8)*DIM + n) = q;
            }
        }
    }
}

// gate finalize
__global__ void gate_fin_k(const float* __restrict__ nb2, const float* __restrict__ eps,
                           float* __restrict__ mask) {
    int idx = blockIdx.x*blockDim.x + threadIdx.x;
    if (idx >= 2*NE) return;
    int inst = idx / NE;
    const float* p = g_PL + (size_t)idx*8;
    float4 a = *(const float4*)p;
    float4 b = *(const float4*)(p + 4);
    float s = ((a.x + a.y) + (a.z + a.w)) + ((b.x + b.y) + (b.z + b.w));
    mask[idx] = gate_fn(s + nb2[inst], eps[idx]);
}

// ================= GEMM 2: scores ==========================================
__global__ void __launch_bounds__(256) scores_mm_k(float* __restrict__ out)
{
    __shared__ __align__(1024) uint8_t sA[2][16384];
    __shared__ __align__(1024) uint8_t sB[2][8192];
    int bx = blockIdx.x, by = blockIdx.y;
    int tid = threadIdx.x;
    uint32_t aA0 = smem_u32(sA[0]), aA1 = smem_u32(sA[1]);
    uint32_t aB0 = smem_u32(sB[0]), aB1 = smem_u32(sB[1]);

    MmaCtx cx; mma_setup(cx, tid);
    float acc[2][4][4];
    #pragma unroll
    for (int a = 0; a < 2; a++)
        #pragma unroll
        for (int b = 0; b < 4; b++)
            #pragma unroll
            for (int q = 0; q < 4; q++) acc[a][b][q] = 0.f;

    load_a128_async(aA0, g_hrb, by*128, BATCH, 0, tid);
    load_b64_async (aB0, g_e0b, bx*64, NE, 0, tid);
    CPA_COMMIT();
    #pragma unroll
    for (int c = 0; c < NCHUNK; c++) {
        uint32_t curA = (c & 1) ? aA1 : aA0, curB = (c & 1) ? aB1 : aB0;
        if (c + 1 < NCHUNK) {
            uint32_t nxtA = ((c+1) & 1) ? aA1 : aA0, nxtB = ((c+1) & 1) ? aB1 : aB0;
            load_a128_async(nxtA, g_hrb, by*128, BATCH, c+1, tid);
            load_b64_async (nxtB, g_e0b, bx*64, NE, c+1, tid);
            CPA_COMMIT();
            CPA_WAIT(1);
        } else {
            CPA_WAIT(0);
        }
        __syncthreads();
        mma_chunk(cx, curA, curB, acc);
        __syncthreads();
    }

    int lane = tid & 31, w = tid >> 5;
    int wm = w >> 1, wn = w & 1;
    int mrow = lane >> 2, ncol = (lane & 3)*2;
    #pragma unroll
    for (int mt = 0; mt < 2; mt++) {
        int m = by*128 + wm*32 + mt*16 + mrow;
        #pragma unroll
        for (int nt = 0; nt < 4; nt++) {
            int n = bx*64 + wn*32 + nt*8 + ncol;
            if (n < NE) {
                float2 v01, v23;
                v01.x = 1.f/(1.f + __expf(-acc[mt][nt][0]));
                v01.y = 1.f/(1.f + __expf(-acc[mt][nt][1]));
                v23.x = 1.f/(1.f + __expf(-acc[mt][nt][2]));
                v23.y = 1.f/(1.f + __expf(-acc[mt][nt][3]));
                *(float2*)(out + (size_t)m*NE + n) = v01;
                *(float2*)(out + (size_t)(m+8)*NE + n) = v23;
            }
        }
    }
}

// ================= support kernels =================
__global__ void rowptr_k(const int* __restrict__ row, int nnz, int* __restrict__ rowptr) {
    int n = blockIdx.x*blockDim.x + threadIdx.x;
    if (n > NE) return;
    int lo = 0, hi = nnz;
    while (lo < hi) { int mid = (lo+hi) >> 1; if (row[mid] < n) lo = mid+1; else hi = mid; }
    rowptr[n] = lo;
}

// edge gate: warp per ROW; U row + W2 cached (R13 measured best)
__global__ void edge_gate_row_k(const int* __restrict__ rowptr, const int* __restrict__ col,
                                const float* __restrict__ adj_val,
                                const float* __restrict__ W2, const float* __restrict__ b2,
                                const float* __restrict__ eps, float* __restrict__ new_edge) {
    int r = (blockIdx.x*blockDim.x + threadIdx.x) >> 5;
    int lane = threadIdx.x & 31;
    if (r >= NE) return;
    int s = rowptr[r], e = rowptr[r+1];
    if (s >= e) return;

    uint4 uu = {0,0,0,0};
    float4 w01 = {0,0,0,0}, w23 = {0,0,0,0};
    if (lane < 25) {
        uu  = __ldg((const uint4*)(g_Ub + (size_t)r*DIM) + lane);
        w01 = __ldg((const float4*)(W2 + lane*8));
        w23 = __ldg((const float4*)(W2 + lane*8 + 4));
    }
    float b2v = b2[0];

    for (int idx = s; idx < e; idx++) {
        int c = __ldg(&col[idx]);
        float acc = 0.f;
        if (lane < 25) {
            uint4 vv = __ldg((const uint4*)(g_Vb + (size_t)c*DIM) + lane);
            const __nv_bfloat162* up = (const __nv_bfloat162*)&uu;
            const __nv_bfloat162* vp = (const __nv_bfloat162*)&vv;
            const float* wp = (const float*)&w01;
            const float* wq = (const float*)&w23;
            #pragma unroll
            for (int t = 0; t < 2; t++) {
                __nv_bfloat162 a = up[t], b = vp[t];
                float h0 = fmaxf(__bfloat162float(a.x) + __bfloat162float(b.x), 0.f);
                float h1 = fmaxf(__bfloat162float(a.y) + __bfloat162float(b.y), 0.f);
                acc = fmaf(h0, wp[2*t], acc);
                acc = fmaf(h1, wp[2*t+1], acc);
            }
            #pragma unroll
            for (int t = 0; t < 2; t++) {
                __nv_bfloat162 a = up[2+t], b = vp[2+t];
                float h0 = fmaxf(__bfloat162float(a.x) + __bfloat162float(b.x), 0.f);
                float h1 = fmaxf(__bfloat162float(a.y) + __bfloat162float(b.y), 0.f);
                acc = fmaf(h0, wq[2*t], acc);
                acc = fmaf(h1, wq[2*t+1], acc);
            }
        }
        acc = warp_sum(acc);
        if (lane == 0)
            new_edge[idx] = __ldg(&adj_val[idx]) * gate_fn(acc + b2v, __ldg(&eps[idx]));
    }
}

// ------- fp16 SpMM family: gather half2 (100 half2/row), fp32 accum --------
// half in -> half out
__global__ void spmm_hh(const int* __restrict__ rowptr, const int* __restrict__ col,
                        const float* __restrict__ val, const __half* __restrict__ x,
                        __half* __restrict__ y) {
    int r = (blockIdx.x*blockDim.x + threadIdx.x) >> 5;
    int lane = threadIdx.x & 31;
    if (r >= NE) return;
    float2 a[4];
    #pragma unroll
    for (int u = 0; u < 4; u++) { a[u].x = 0.f; a[u].y = 0.f; }
    bool p3 = lane < 4;
    int s = rowptr[r], e = rowptr[r+1];
    for (int idx = s; idx < e; idx++) {
        int c = __ldg(&col[idx]);
        float v = __ldg(&val[idx]);
        const __half2* xr = (const __half2*)(x + (size_t)c*DIM);
        #pragma unroll
        for (int u = 0; u < 3; u++) {
            float2 f = __half22float2(__ldg(&xr[lane + 32*u]));
            a[u].x = fmaf(v, f.x, a[u].x);
            a[u].y = fmaf(v, f.y, a[u].y);
        }
        if (p3) {
            float2 f = __half22float2(__ldg(&xr[lane + 96]));
            a[3].x = fmaf(v, f.x, a[3].x);
            a[3].y = fmaf(v, f.y, a[3].y);
        }
    }
    __half2* yr = (__half2*)(y + (size_t)r*DIM);
    #pragma unroll
    for (int u = 0; u < 3; u++) yr[lane + 32*u] = __floats2half2_rn(a[u].x, a[u].y);
    if (p3) yr[lane + 96] = __floats2half2_rn(a[3].x, a[3].y);
}

// half in -> float out
__global__ void spmm_hf(const int* __restrict__ rowptr, const int* __restrict__ col,
                        const float* __restrict__ val, const __half* __restrict__ x,
                        float* __restrict__ y) {
    int r = (blockIdx.x*blockDim.x + threadIdx.x) >> 5;
    int lane = threadIdx.x & 31;
    if (r >= NE) return;
    float2 a[4];
    #pragma unroll
    for (int u = 0; u < 4; u++) { a[u].x = 0.f; a[u].y = 0.f; }
    bool p3 = lane < 4;
    int s = rowptr[r], e = rowptr[r+1];
    for (int idx = s; idx < e; idx++) {
        int c = __ldg(&col[idx]);
        float v = __ldg(&val[idx]);
        const __half2* xr = (const __half2*)(x + (size_t)c*DIM);
        #pragma unroll
        for (int u = 0; u < 3; u++) {
            float2 f = __half22float2(__ldg(&xr[lane + 32*u]));
            a[u].x = fmaf(v, f.x, a[u].x);
            a[u].y = fmaf(v, f.y, a[u].y);
        }
        if (p3) {
            float2 f = __half22float2(__ldg(&xr[lane + 96]));
            a[3].x = fmaf(v, f.x, a[3].x);
            a[3].y = fmaf(v, f.y, a[3].y);
        }
    }
    float2* yr = (float2*)(y + (size_t)r*DIM);
    #pragma unroll
    for (int u = 0; u < 3; u++) yr[lane + 32*u] = a[u];
    if (p3) yr[lane + 96] = a[3];
}

// half in -> mix with self row -> half out
__global__ void spmm_mix_hh(const int* __restrict__ rowptr, const int* __restrict__ col,
                            const float* __restrict__ val, const __half* __restrict__ x,
                            const float* __restrict__ mask, __half* __restrict__ y) {
    int r = (blockIdx.x*blockDim.x + threadIdx.x) >> 5;
    int lane = threadIdx.x & 31;
    if (r >= NE) return;
    float2 a[4];
    #pragma unroll
    for (int u = 0; u < 4; u++) { a[u].x = 0.f; a[u].y = 0.f; }
    bool p3 = lane < 4;
    int s = rowptr[r], e = rowptr[r+1];
    for (int idx = s; idx < e; idx++) {
        int c = __ldg(&col[idx]);
        float v = __ldg(&val[idx]);
        const __half2* xr = (const __half2*)(x + (size_t)c*DIM);
        #pragma unroll
        for (int u = 0; u < 3; u++) {
            float2 f = __half22float2(__ldg(&xr[lane + 32*u]));
            a[u].x = fmaf(v, f.x, a[u].x);
            a[u].y = fmaf(v, f.y, a[u].y);
        }
        if (p3) {
            float2 f = __half22float2(__ldg(&xr[lane + 96]));
            a[3].x = fmaf(v, f.x, a[3].x);
            a[3].y = fmaf(v, f.y, a[3].y);
        }
    }
    float m = mask[r], im = 1.f - m;
    const __half2* xs = (const __half2*)(x + (size_t)r*DIM);
    __half2* yr = (__half2*)(y + (size_t)r*DIM);
    #pragma unroll
    for (int u = 0; u < 3; u++) {
        float2 sv = __half22float2(xs[lane + 32*u]);
        yr[lane + 32*u] = __floats2half2_rn(m*sv.x + im*a[u].x, m*sv.y + im*a[u].y);
    }
    if (p3) {
        float2 sv = __half22float2(xs[lane + 96]);
        yr[lane + 96] = __floats2half2_rn(m*sv.x + im*a[3].x, m*sv.y + im*a[3].y);
    }
}

// elementwise mix on halves
__global__ void mix_h_k(const __half* __restrict__ x, const __half* __restrict__ mp,
                        const float* __restrict__ mask, __half* __restrict__ y) {
    int idx = blockIdx.x*blockDim.x + threadIdx.x;
    if (idx >= NE*100) return;
    int row = idx / 100;
    float m = mask[row], im = 1.f - m;
    float2 a = __half22float2(__ldg((const __half2*)x + idx));
    float2 b = __half22float2(__ldg((const __half2*)mp + idx));
    ((__half2*)y)[idx] = __floats2half2_rn(m*a.x + im*b.x, m*a.y + im*b.y);
}

// RESCAL -> bf16 hrb
__global__ void rescal_k(const float* __restrict__ e0, const float* __restrict__ rel_emb,
                         const int* __restrict__ sub, const int* __restrict__ rel) {
    int b = blockIdx.x;
    int j = threadIdx.x;
    __shared__ float ls[DIM];
    const float* lhs = e0 + (size_t)sub[b]*DIM;
    if (j < DIM) ls[j] = lhs[j];
    __syncthreads();
    if (j < DIM) {
        const float* R = rel_emb + (size_t)rel[b]*RELD;
        float acc = 0.f;
        #pragma unroll 4
        for (int k = 0; k < DIM; k++) acc = fmaf(ls[k], R[(size_t)k*DIM + j], acc);
        g_hrb[(size_t)b*KPAD + j] = __float2bfloat16(acc);
    }
}

// ================= launch ==================================================
extern "C" void kernel_launch(void* const* d_in, const int* in_sizes, int n_in,
                              void* d_out, int out_size) {
    const float* e0       = (const float*)d_in[0];
    const float* rel_emb  = (const float*)d_in[1];
    const float* nW1      = (const float*)d_in[2];
    const float* nb1      = (const float*)d_in[3];
    const float* nW2      = (const float*)d_in[4];
    const float* nb2      = (const float*)d_in[5];
    const float* eW1      = (const float*)d_in[6];
    const float* eb1      = (const float*)d_in[7];
    const float* eW2      = (const float*)d_in[8];
    const float* eb2      = (const float*)d_in[9];
    const int*   adj_row  = (const int*)d_in[10];
    const int*   adj_col  = (const int*)d_in[11];
    const float* adj_val  = (const float*)d_in[12];
    const int*   rw_row   = (const int*)d_in[13];
    const int*   rw_col   = (const int*)d_in[14];
    const float* rw_val   = (const float*)d_in[15];
    const float* node_eps = (const float*)d_in[16];
    const float* edge_eps = (const float*)d_in[17];
    const int*   sub      = (const int*)d_in[18];
    const int*   rel      = (const int*)d_in[19];

    int E   = in_sizes[10];
    int Erw = in_sizes[13];

    float* out        = (float*)d_out;
    float* out_scores = out;
    float* out_xnd    = out + (size_t)BATCH*NE;
    float* out_xed    = out_xnd + (size_t)NE*DIM;

    float *NMASK, *NEWEDGE;
    __half *E0H, *X1H, *X2H, *MPH, *E2H;
    int *RPA, *RPR;
    cudaGetSymbolAddress((void**)&E0H, g_e0h);
    cudaGetSymbolAddress((void**)&X1H, g_X1h);
    cudaGetSymbolAddress((void**)&X2H, g_X2h);
    cudaGetSymbolAddress((void**)&MPH, g_MPh);
    cudaGetSymbolAddress((void**)&E2H, g_E2h);
    cudaGetSymbolAddress((void**)&NMASK, g_NMASK);
    cudaGetSymbolAddress((void**)&NEWEDGE, g_NEWEDGE);
    cudaGetSymbolAddress((void**)&RPA, g_rp_adj);
    cudaGetSymbolAddress((void**)&RPR, g_rp_rw);

    static cudaStream_t s1 = nullptr, s2 = nullptr;
    static cudaEvent_t evFork0, evConv, evRw, evUV, evMP, evS1, evS2;
    if (!s1) {
        cudaStreamCreateWithFlags(&s1, cudaStreamNonBlocking);
        cudaStreamCreateWithFlags(&s2, cudaStreamNonBlocking);
        cudaEventCreateWithFlags(&evFork0, cudaEventDisableTiming);
        cudaEventCreateWithFlags(&evConv,  cudaEventDisableTiming);
        cudaEventCreateWithFlags(&evRw,    cudaEventDisableTiming);
        cudaEventCreateWithFlags(&evUV,    cudaEventDisableTiming);
        cudaEventCreateWithFlags(&evMP,    cudaEventDisableTiming);
        cudaEventCreateWithFlags(&evS1,    cudaEventDisableTiming);
        cudaEventCreateWithFlags(&evS2,    cudaEventDisableTiming);
    }

    const int SPB = (NE*32 + 255)/256;
    const int MT  = (NE + 127)/128;

    // ---- fork point ----
    cudaEventRecord(evFork0, 0);

    // ---- main stream: prep ----
    rowptr_k<<<(NE+1+255)/256, 256>>>(rw_row, Erw, RPR);
    conv_e0_k<<<(NE*50 + 255)/256, 256>>>(e0);
    cudaEventRecord(evConv, 0);
    rowptr_k<<<(NE+1+255)/256, 256>>>(adj_row, E, RPA);
    dim3 wgrid((DIM*DIM + 255)/256, 4);
    conv_w_k<<<wgrid, 256>>>(nW1, eW1);

    // ---- s1: rescal -> scores ----
    cudaStreamWaitEvent(s1, evFork0, 0);
    rescal_k<<<BATCH, 256, 0, s1>>>(e0, rel_emb, sub, rel);
    cudaStreamWaitEvent(s1, evConv, 0);
    dim3 sgrid((NE + 63)/64, BATCH/128);
    scores_mm_k<<<sgrid, 256, 0, s1>>>(out_scores);
    cudaEventRecord(evS1, s1);

    // ---- s2: edge-branch rw propagation (fp16) ----
    cudaStreamWaitEvent(s2, evConv, 0);
    spmm_hh<<<SPB, 256, 0, s2>>>(RPR, rw_col, rw_val, E0H, MPH);
    cudaEventRecord(evMP, s2);
    spmm_hh<<<SPB, 256, 0, s2>>>(RPR, rw_col, rw_val, MPH, E2H);

    // ---- main: UV half first, node half second ----
    dim3 mgrid(MT, 4, 2);
    mm_e0w_k<<<mgrid, 256>>>(nb1, eb1, nW2, 2);
    cudaEventRecord(evUV, 0);
    mm_e0w_k<<<mgrid, 256>>>(nb1, eb1, nW2, 0);
    gate_fin_k<<<(2*NE + 255)/256, 256>>>(nb2, node_eps, NMASK);

    // ---- s2: edge gate + final edge spmm ----
    cudaStreamWaitEvent(s2, evUV, 0);
    edge_gate_row_k<<<SPB, 256, 0, s2>>>(RPA, adj_col, adj_val,
                                         eW2 + DIM, eb2 + 1, edge_eps + E, NEWEDGE);
    spmm_hf<<<SPB, 256, 0, s2>>>(RPA, adj_col, NEWEDGE, E2H, out_xed);
    cudaEventRecord(evS2, s2);

    // ---- main: node-drop branch (fp16 intermediates) ----
    cudaStreamWaitEvent(0, evMP, 0);
    mix_h_k<<<(NE*100 + 255)/256, 256>>>(E0H, MPH, NMASK, X1H);
    spmm_hh<<<SPB, 256>>>(RPA, adj_col, adj_val, X1H, X2H);
    spmm_mix_hh<<<SPB, 256>>>(RPR, rw_col, rw_val, X2H, NMASK + NE, X1H);
    spmm_hf<<<SPB, 256>>>(RPA, adj_col, adj_val, X1H, out_xnd);

    // ---- join ----
    cudaStreamWaitEvent(0, evS1, 0);
    cudaStreamWaitEvent(0, evS2, 0);
}

// round 15
// speedup vs baseline: 1.1146x; 1.0269x over previous
#include <cuda_runtime.h>
#include <cuda_bf16.h>
#include <cuda_fp16.h>
#include <math.h>
#include <stdint.h>

#define NE    50000
#define DIM   200
#define BATCH 1024
#define EMAX  400000
#define RELD  40000
#define KPAD  256
#define NPAD  256

// ---------------- scratch (zero-init => pad regions stay 0)
__device__ __align__(16) __nv_bfloat16 g_e0b[(size_t)NE*KPAD];
__device__ __align__(16) __nv_bfloat16 g_hrb[(size_t)BATCH*KPAD];
__device__ __align__(16) __nv_bfloat16 g_Wtb[(size_t)4*NPAD*KPAD];
__device__ __align__(16) __nv_bfloat16 g_Ub[(size_t)NE*DIM];
__device__ __align__(16) __nv_bfloat16 g_Vb[(size_t)NE*DIM];
__device__ __align__(16) float g_PL[(size_t)2*NE*8];
__device__ __align__(16) __half g_e0h[(size_t)NE*DIM];
__device__ __align__(16) __half g_X1h[(size_t)NE*DIM];
__device__ __align__(16) __half g_X2h[(size_t)NE*DIM];
__device__ __align__(16) __half g_MPh[(size_t)NE*DIM];
__device__ __align__(16) __half g_E2h[(size_t)NE*DIM];
__device__ float g_NMASK[2*NE];
__device__ float g_NEWEDGE[EMAX];
__device__ int   g_rp_adj[NE+1];
__device__ int   g_rp_rw [NE+1];

// ================= helpers =================
__device__ __forceinline__ uint32_t smem_u32(const void* p) {
    uint32_t a;
    asm("{ .reg .u64 t; cvta.to.shared.u64 t, %1; cvt.u32.u64 %0, t; }" : "=r"(a) : "l"(p));
    return a;
}
#define SW128(o) ((o) ^ (((o) >> 3) & 0x70))

__device__ __forceinline__ void ldmx4(uint32_t* r, uint32_t addr) {
    asm volatile("ldmatrix.sync.aligned.m8n8.x4.shared.b16 {%0,%1,%2,%3}, [%4];"
        : "=r"(r[0]), "=r"(r[1]), "=r"(r[2]), "=r"(r[3]) : "r"(addr));
}
__device__ __forceinline__ void mma16816(float* c, const uint32_t* a, const uint32_t* b) {
    asm volatile("mma.sync.aligned.m16n8k16.row.col.f32.bf16.bf16.f32 "
        "{%0,%1,%2,%3}, {%4,%5,%6,%7}, {%8,%9}, {%0,%1,%2,%3};"
        : "+f"(c[0]), "+f"(c[1]), "+f"(c[2]), "+f"(c[3])
        : "r"(a[0]), "r"(a[1]), "r"(a[2]), "r"(a[3]), "r"(b[0]), "r"(b[1]));
}
__device__ __forceinline__ void cpa16(uint32_t dst, const void* src) {
    asm volatile("cp.async.cg.shared.global [%0], [%1], 16;" :: "r"(dst), "l"(src));
}
#define CPA_COMMIT() asm volatile("cp.async.commit_group;" ::: "memory")
#define CPA_WAIT(n)  asm volatile("cp.async.wait_group %0;" :: "n"(n) : "memory")

__device__ __forceinline__ float gate_fn(float logits, float u) {
    const float bias = 1e-4f;
    float eps = (2.f*bias - 1.f)*u + (1.f - bias);
    float t = 2.f*(__logf(eps) - __logf(1.f - eps) + logits);
    return 1.f/(1.f + __expf(-t));
}
__device__ __forceinline__ float warp_sum(float v) {
    #pragma unroll
    for (int o = 16; o; o >>= 1) v += __shfl_xor_sync(0xffffffffu, v, o);
    return v;
}

// ================= conversion kernels =================
__global__ void conv_e0_k(const float* __restrict__ e0) {
    int t = blockIdx.x*blockDim.x + threadIdx.x;
    if (t >= NE*50) return;
    int row = t/50, k = (t%50)*4;
    float4 v = *(const float4*)(e0 + (size_t)row*DIM + k);
    __nv_bfloat162 p0, p1;
    p0.x = __float2bfloat16(v.x); p0.y = __float2bfloat16(v.y);
    p1.x = __float2bfloat16(v.z); p1.y = __float2bfloat16(v.w);
    __nv_bfloat16* d = g_e0b + (size_t)row*KPAD + k;
    *(__nv_bfloat162*)(d)     = p0;
    *(__nv_bfloat162*)(d + 2) = p1;
    __half2 h0 = __floats2half2_rn(v.x, v.y);
    __half2 h1 = __floats2half2_rn(v.z, v.w);
    __half* dh = g_e0h + (size_t)row*DIM + k;
    *(__half2*)(dh)     = h0;
    *(__half2*)(dh + 2) = h1;
}

__global__ void conv_w_k(const float* __restrict__ nW1, const float* __restrict__ eW1) {
    int inst = blockIdx.y;
    int t = blockIdx.x*blockDim.x + threadIdx.x;
    if (t >= DIM*DIM) return;
    const float* src;
    if (inst == 0)      src = nW1;
    else if (inst == 1) src = nW1 + RELD;
    else if (inst == 2) src = eW1 + 2*RELD;
    else                src = eW1 + 3*RELD;
    int n = t/DIM, k = t%DIM;
    g_Wtb[(size_t)inst*NPAD*KPAD + (size_t)n*KPAD + k] = __float2bfloat16(src[(size_t)k*DIM + n]);
}

// ================= HMMA machinery ==========================================
struct MmaCtx {
    int aAtom0, aAtom1, aLine0, aLine1, aKadd;
    int bAtom0, bAtom1, bLine0, bLine1, bKadd;
};
__device__ __forceinline__ void mma_setup(MmaCtx& cx, int tid) {
    int lane = tid & 31, i = lane >> 3, rr = lane & 7;
    int w = tid >> 5;
    int wm = w >> 1, wn = w & 1;
    int ar0 = wm*32 + (i&1)*8 + rr;
    int ar1 = ar0 + 16;
    int br0 = wn*32 + (i>>1)*8 + rr;
    int br1 = br0 + 16;
    cx.aAtom0 = (ar0>>3)*1024; cx.aLine0 = (ar0&7)*128;
    cx.aAtom1 = (ar1>>3)*1024; cx.aLine1 = (ar1&7)*128;
    cx.aKadd = (i>>1)*16;
    cx.bAtom0 = (br0>>3)*1024; cx.bLine0 = (br0&7)*128;
    cx.bAtom1 = (br1>>3)*1024; cx.bLine1 = (br1&7)*128;
    cx.bKadd = (i&1)*16;
}
// ksn = number of k16 steps to execute in this chunk (4 full, 1 tail)
__device__ __forceinline__ void mma_chunk(const MmaCtx& cx, uint32_t aA, uint32_t aB,
                                          float acc[2][4][4], int ksn) {
    #pragma unroll
    for (int ks = 0; ks < 4; ks++) {
        if (ks >= ksn) break;
        int kb = ks*32;
        uint32_t a0[4], a1[4], b0[4], b1[4];
        ldmx4(a0, aA + cx.aAtom0 + SW128(cx.aLine0 + kb + cx.aKadd));
        ldmx4(a1, aA + cx.aAtom1 + SW128(cx.aLine1 + kb + cx.aKadd));
        ldmx4(b0, aB + cx.bAtom0 + SW128(cx.bLine0 + kb + cx.bKadd));
        ldmx4(b1, aB + cx.bAtom1 + SW128(cx.bLine1 + kb + cx.bKadd));
        mma16816(acc[0][0], a0, b0);
        mma16816(acc[0][1], a0, b0 + 2);
        mma16816(acc[0][2], a0, b1);
        mma16816(acc[0][3], a0, b1 + 2);
        mma16816(acc[1][0], a1, b0);
        mma16816(acc[1][1], a1, b0 + 2);
        mma16816(acc[1][2], a1, b1);
        mma16816(acc[1][3], a1, b1 + 2);
    }
}
// full chunk loaders (8 q per row)
__device__ __forceinline__ void load_a128_async(uint32_t sA, const __nv_bfloat16* Ag,
                                                int row0, int rmax, int c, int tid) {
    #pragma unroll
    for (int i = 0; i < 4; i++) {
        int idx = tid + i*256;
        int r = idx >> 3, q = idx & 7;
        int gr = row0 + r; if (gr >= rmax) gr = 0;
        uint32_t off = (uint32_t)((r>>3)*1024) + SW128((uint32_t)((r&7)*128 + q*16));
        cpa16(sA + off, Ag + (size_t)gr*KPAD + c*64 + q*8);
    }
}
__device__ __forceinline__ void load_b64_async(uint32_t sB, const __nv_bfloat16* Bg,
                                               int row0, int rmax, int c, int tid) {
    #pragma unroll
    for (int i = 0; i < 2; i++) {
        int idx = tid + i*256;
        int r = idx >> 3, q = idx & 7;
        int gr = row0 + r; if (gr >= rmax) gr = 0;
        uint32_t off = (uint32_t)((r>>3)*1024) + SW128((uint32_t)((r&7)*128 + q*16));
        cpa16(sB + off, Bg + (size_t)gr*KPAD + c*64 + q*8);
    }
}
// tail chunk loaders: only q=0,1 (cols c*64 .. c*64+15)
__device__ __forceinline__ void load_a128_tail(uint32_t sA, const __nv_bfloat16* Ag,
                                               int row0, int rmax, int c, int tid) {
    // 128 rows x 2 q = 256 elems
    int r = tid >> 1, q = tid & 1;
    int gr = row0 + r; if (gr >= rmax) gr = 0;
    uint32_t off = (uint32_t)((r>>3)*1024) + SW128((uint32_t)((r&7)*128 + q*16));
    cpa16(sA + off, Ag + (size_t)gr*KPAD + c*64 + q*8);
}
__device__ __forceinline__ void load_b64_tail(uint32_t sB, const __nv_bfloat16* Bg,
                                              int row0, int rmax, int c, int tid) {
    // 64 rows x 2 q = 128 elems
    if (tid < 128) {
        int r = tid >> 1, q = tid & 1;
        int gr = row0 + r; if (gr >= rmax) gr = 0;
        uint32_t off = (uint32_t)((r>>3)*1024) + SW128((uint32_t)((r&7)*128 + q*16));
        cpa16(sB + off, Bg + (size_t)gr*KPAD + c*64 + q*8);
    }
}

// ================= GEMM 1: e0 @ W; split by inst0; K=208 truncated =========
__global__ void __launch_bounds__(256) mm_e0w_k(
    const float* __restrict__ nb1, const float* __restrict__ eb1,
    const float* __restrict__ nW2, int inst0)
{
    __shared__ __align__(1024) uint8_t sA[2][16384];
    __shared__ __align__(1024) uint8_t sB[2][8192];
    int bm = blockIdx.x, nt64 = blockIdx.y, inst = inst0 + blockIdx.z;
    int tid = threadIdx.x;
    uint32_t aA0 = smem_u32(sA[0]), aA1 = smem_u32(sA[1]);
    uint32_t aB0 = smem_u32(sB[0]), aB1 = smem_u32(sB[1]);

    MmaCtx cx; mma_setup(cx, tid);
    float acc[2][4][4];
    #pragma unroll
    for (int a = 0; a < 2; a++)
        #pragma unroll
        for (int b = 0; b < 4; b++)
            #pragma unroll
            for (int q = 0; q < 4; q++) acc[a][b][q] = 0.f;

    const __nv_bfloat16* Bg = g_Wtb + (size_t)inst*NPAD*KPAD;

    load_a128_async(aA0, g_e0b, bm*128, NE, 0, tid);
    load_b64_async (aB0, Bg, nt64*64, NPAD, 0, tid);
    CPA_COMMIT();
    #pragma unroll
    for (int c = 0; c < 4; c++) {
        uint32_t curA = (c & 1) ? aA1 : aA0, curB = (c & 1) ? aB1 : aB0;
        if (c + 1 < 4) {
            uint32_t nxtA = ((c+1) & 1) ? aA1 : aA0, nxtB = ((c+1) & 1) ? aB1 : aB0;
            if (c + 1 < 3) {
                load_a128_async(nxtA, g_e0b, bm*128, NE, c+1, tid);
                load_b64_async (nxtB, Bg, nt64*64, NPAD, c+1, tid);
            } else {
                load_a128_tail(nxtA, g_e0b, bm*128, NE, 3, tid);
                load_b64_tail (nxtB, Bg, nt64*64, NPAD, 3, tid);
            }
            CPA_COMMIT();
            CPA_WAIT(1);
        } else {
            CPA_WAIT(0);
        }
        __syncthreads();
        mma_chunk(cx, curA, curB, acc, (c < 3) ? 4 : 1);
        __syncthreads();
    }

    int lane = tid & 31, w = tid >> 5;
    int wm = w >> 1, wn = w & 1;
    int mrow = lane >> 2, ncol = (lane & 3)*2;
    int nbase = nt64*64 + wn*32;

    if (inst < 2) {
        const float* bias = nb1 + inst*DIM;
        const float* W2 = nW2 + inst*DIM;
        int seg = nt64*2 + wn;
        #pragma unroll
        for (int mt = 0; mt < 2; mt++) {
            float p0 = 0.f, p1 = 0.f;
            #pragma unroll
            for (int nt = 0; nt < 4; nt++) {
                int n = nbase + nt*8 + ncol;
                float b0 = 0.f, b1v = 0.f, w0 = 0.f, w1 = 0.f;
                if (n < DIM)     { b0 = bias[n];   w0 = W2[n];   }
                if (n + 1 < DIM) { b1v = bias[n+1]; w1 = W2[n+1]; }
                p0 = fmaf(fmaxf(acc[mt][nt][0] + b0, 0.f), w0, p0);
                p0 = fmaf(fmaxf(acc[mt][nt][1] + b1v, 0.f), w1, p0);
                p1 = fmaf(fmaxf(acc[mt][nt][2] + b0, 0.f), w0, p1);
                p1 = fmaf(fmaxf(acc[mt][nt][3] + b1v, 0.f), w1, p1);
            }
            p0 += __shfl_xor_sync(0xffffffffu, p0, 1);
            p0 += __shfl_xor_sync(0xffffffffu, p0, 2);
            p1 += __shfl_xor_sync(0xffffffffu, p1, 1);
            p1 += __shfl_xor_sync(0xffffffffu, p1, 2);
            if ((lane & 3) == 0) {
                int m0 = bm*128 + wm*32 + mt*16 + mrow;
                if (m0 < NE)     g_PL[((size_t)inst*NE + m0)*8 + seg] = p0;
                if (m0 + 8 < NE) g_PL[((size_t)inst*NE + m0 + 8)*8 + seg] = p1;
            }
        }
    } else {
        __nv_bfloat16* C = (inst == 2) ? g_Ub : g_Vb;
        const float* bias = (inst == 3) ? (eb1 + DIM) : nullptr;
        #pragma unroll
        for (int mt = 0; mt < 2; mt++) {
            int m = bm*128 + wm*32 + mt*16 + mrow;
            if (m >= NE) continue;
            #pragma unroll
            for (int nt = 0; nt < 4; nt++) {
                int n = nbase + nt*8 + ncol;
                if (n >= DIM) continue;
                float b0 = bias ? bias[n] : 0.f, b1 = bias ? bias[n+1] : 0.f;
                __nv_bfloat162 p, q;
                p.x = __float2bfloat16(acc[mt][nt][0] + b0);
                p.y = __float2bfloat16(acc[mt][nt][1] + b1);
                q.x = __float2bfloat16(acc[mt][nt][2] + b0);
                q.y = __float2bfloat16(acc[mt][nt][3] + b1);
                *(__nv_bfloat162*)(C + (size_t)m*DIM + n) = p;
                if (m + 8 < NE) *(__nv_bfloat162*)(C + (size_t)(m+8)*DIM + n) = q;
            }
        }
    }
}

// gate finalize
__global__ void gate_fin_k(const float* __restrict__ nb2, const float* __restrict__ eps,
                           float* __restrict__ mask) {
    int idx = blockIdx.x*blockDim.x + threadIdx.x;
    if (idx >= 2*NE) return;
    int inst = idx / NE;
    const float* p = g_PL + (size_t)idx*8;
    float4 a = *(const float4*)p;
    float4 b = *(const float4*)(p + 4);
    float s = ((a.x + a.y) + (a.z + a.w)) + ((b.x + b.y) + (b.z + b.w));
    mask[idx] = gate_fn(s + nb2[inst], eps[idx]);
}

// ================= GEMM 2: scores; K=208 truncated =========================
__global__ void __launch_bounds__(256) scores_mm_k(float* __restrict__ out)
{
    __shared__ __align__(1024) uint8_t sA[2][16384];
    __shared__ __align__(1024) uint8_t sB[2][8192];
    int bx = blockIdx.x, by = blockIdx.y;
    int tid = threadIdx.x;
    uint32_t aA0 = smem_u32(sA[0]), aA1 = smem_u32(sA[1]);
    uint32_t aB0 = smem_u32(sB[0]), aB1 = smem_u32(sB[1]);

    MmaCtx cx; mma_setup(cx, tid);
    float acc[2][4][4];
    #pragma unroll
    for (int a = 0; a < 2; a++)
        #pragma unroll
        for (int b = 0; b < 4; b++)
            #pragma unroll
            for (int q = 0; q < 4; q++) acc[a][b][q] = 0.f;

    load_a128_async(aA0, g_hrb, by*128, BATCH, 0, tid);
    load_b64_async (aB0, g_e0b, bx*64, NE, 0, tid);
    CPA_COMMIT();
    #pragma unroll
    for (int c = 0; c < 4; c++) {
        uint32_t curA = (c & 1) ? aA1 : aA0, curB = (c & 1) ? aB1 : aB0;
        if (c + 1 < 4) {
            uint32_t nxtA = ((c+1) & 1) ? aA1 : aA0, nxtB = ((c+1) & 1) ? aB1 : aB0;
            if (c + 1 < 3) {
                load_a128_async(nxtA, g_hrb, by*128, BATCH, c+1, tid);
                load_b64_async (nxtB, g_e0b, bx*64, NE, c+1, tid);
            } else {
                load_a128_tail(nxtA, g_hrb, by*128, BATCH, 3, tid);
                load_b64_tail (nxtB, g_e0b, bx*64, NE, 3, tid);
            }
            CPA_COMMIT();
            CPA_WAIT(1);
        } else {
            CPA_WAIT(0);
        }
        __syncthreads();
        mma_chunk(cx, curA, curB, acc, (c < 3) ? 4 : 1);
        __syncthreads();
    }

    int lane = tid & 31, w = tid >> 5;
    int wm = w >> 1, wn = w & 1;
    int mrow = lane >> 2, ncol = (lane & 3)*2;
    #pragma unroll
    for (int mt = 0; mt < 2; mt++) {
        int m = by*128 + wm*32 + mt*16 + mrow;
        #pragma unroll
        for (int nt = 0; nt < 4; nt++) {
            int n = bx*64 + wn*32 + nt*8 + ncol;
            if (n < NE) {
                float2 v01, v23;
                v01.x = 1.f/(1.f + __expf(-acc[mt][nt][0]));
                v01.y = 1.f/(1.f + __expf(-acc[mt][nt][1]));
                v23.x = 1.f/(1.f + __expf(-acc[mt][nt][2]));
                v23.y = 1.f/(1.f + __expf(-acc[mt][nt][3]));
                *(float2*)(out + (size_t)m*NE + n) = v01;
                *(float2*)(out + (size_t)(m+8)*NE + n) = v23;
            }
        }
    }
}

// ================= support kernels =================
__global__ void rowptr_k(const int* __restrict__ row, int nnz, int* __restrict__ rowptr) {
    int n = blockIdx.x*blockDim.x + threadIdx.x;
    if (n > NE) return;
    int lo = 0, hi = nnz;
    while (lo < hi) { int mid = (lo+hi) >> 1; if (row[mid] < n) lo = mid+1; else hi = mid; }
    rowptr[n] = lo;
}

// edge gate: warp per ROW; U row + W2 cached
__global__ void edge_gate_row_k(const int* __restrict__ rowptr, const int* __restrict__ col,
                                const float* __restrict__ adj_val,
                                const float* __restrict__ W2, const float* __restrict__ b2,
                                const float* __restrict__ eps, float* __restrict__ new_edge) {
    int r = (blockIdx.x*blockDim.x + threadIdx.x) >> 5;
    int lane = threadIdx.x & 31;
    if (r >= NE) return;
    int s = rowptr[r], e = rowptr[r+1];
    if (s >= e) return;

    uint4 uu = {0,0,0,0};
    float4 w01 = {0,0,0,0}, w23 = {0,0,0,0};
    if (lane < 25) {
        uu  = __ldg((const uint4*)(g_Ub + (size_t)r*DIM) + lane);
        w01 = __ldg((const float4*)(W2 + lane*8));
        w23 = __ldg((const float4*)(W2 + lane*8 + 4));
    }
    float b2v = b2[0];

    for (int idx = s; idx < e; idx++) {
        int c = __ldg(&col[idx]);
        float acc = 0.f;
        if (lane < 25) {
            uint4 vv = __ldg((const uint4*)(g_Vb + (size_t)c*DIM) + lane);
            const __nv_bfloat162* up = (const __nv_bfloat162*)&uu;
            const __nv_bfloat162* vp = (const __nv_bfloat162*)&vv;
            const float* wp = (const float*)&w01;
            const float* wq = (const float*)&w23;
            #pragma unroll
            for (int t = 0; t < 2; t++) {
                __nv_bfloat162 a = up[t], b = vp[t];
                float h0 = fmaxf(__bfloat162float(a.x) + __bfloat162float(b.x), 0.f);
                float h1 = fmaxf(__bfloat162float(a.y) + __bfloat162float(b.y), 0.f);
                acc = fmaf(h0, wp[2*t], acc);
                acc = fmaf(h1, wp[2*t+1], acc);
            }
            #pragma unroll
            for (int t = 0; t < 2; t++) {
                __nv_bfloat162 a = up[2+t], b = vp[2+t];
                float h0 = fmaxf(__bfloat162float(a.x) + __bfloat162float(b.x), 0.f);
                float h1 = fmaxf(__bfloat162float(a.y) + __bfloat162float(b.y), 0.f);
                acc = fmaf(h0, wq[2*t], acc);
                acc = fmaf(h1, wq[2*t+1], acc);
            }
        }
        acc = warp_sum(acc);
        if (lane == 0)
            new_edge[idx] = __ldg(&adj_val[idx]) * gate_fn(acc + b2v, __ldg(&eps[idx]));
    }
}

// ------- fp16 SpMM family --------
__global__ void spmm_hh(const int* __restrict__ rowptr, const int* __restrict__ col,
                        const float* __restrict__ val, const __half* __restrict__ x,
                        __half* __restrict__ y) {
    int r = (blockIdx.x*blockDim.x + threadIdx.x) >> 5;
    int lane = threadIdx.x & 31;
    if (r >= NE) return;
    float2 a[4];
    #pragma unroll
    for (int u = 0; u < 4; u++) { a[u].x = 0.f; a[u].y = 0.f; }
    bool p3 = lane < 4;
    int s = rowptr[r], e = rowptr[r+1];
    for (int idx = s; idx < e; idx++) {
        int c = __ldg(&col[idx]);
        float v = __ldg(&val[idx]);
        const __half2* xr = (const __half2*)(x + (size_t)c*DIM);
        #pragma unroll
        for (int u = 0; u < 3; u++) {
            float2 f = __half22float2(__ldg(&xr[lane + 32*u]));
            a[u].x = fmaf(v, f.x, a[u].x);
            a[u].y = fmaf(v, f.y, a[u].y);
        }
        if (p3) {
            float2 f = __half22float2(__ldg(&xr[lane + 96]));
            a[3].x = fmaf(v, f.x, a[3].x);
            a[3].y = fmaf(v, f.y, a[3].y);
        }
    }
    __half2* yr = (__half2*)(y + (size_t)r*DIM);
    #pragma unroll
    for (int u = 0; u < 3; u++) yr[lane + 32*u] = __floats2half2_rn(a[u].x, a[u].y);
    if (p3) yr[lane + 96] = __floats2half2_rn(a[3].x, a[3].y);
}

__global__ void spmm_hf(const int* __restrict__ rowptr, const int* __restrict__ col,
                        const float* __restrict__ val, const __half* __restrict__ x,
                        float* __restrict__ y) {
    int r = (blockIdx.x*blockDim.x + threadIdx.x) >> 5;
    int lane = threadIdx.x & 31;
    if (r >= NE) return;
    float2 a[4];
    #pragma unroll
    for (int u = 0; u < 4; u++) { a[u].x = 0.f; a[u].y = 0.f; }
    bool p3 = lane < 4;
    int s = rowptr[r], e = rowptr[r+1];
    for (int idx = s; idx < e; idx++) {
        int c = __ldg(&col[idx]);
        float v = __ldg(&val[idx]);
        const __half2* xr = (const __half2*)(x + (size_t)c*DIM);
        #pragma unroll
        for (int u = 0; u < 3; u++) {
            float2 f = __half22float2(__ldg(&xr[lane + 32*u]));
            a[u].x = fmaf(v, f.x, a[u].x);
            a[u].y = fmaf(v, f.y, a[u].y);
        }
        if (p3) {
            float2 f = __half22float2(__ldg(&xr[lane + 96]));
            a[3].x = fmaf(v, f.x, a[3].x);
            a[3].y = fmaf(v, f.y, a[3].y);
        }
    }
    float2* yr = (float2*)(y + (size_t)r*DIM);
    #pragma unroll
    for (int u = 0; u < 3; u++) yr[lane + 32*u] = a[u];
    if (p3) yr[lane + 96] = a[3];
}

__global__ void spmm_mix_hh(const int* __restrict__ rowptr, const int* __restrict__ col,
                            const float* __restrict__ val, const __half* __restrict__ x,
                            const float* __restrict__ mask, __half* __restrict__ y) {
    int r = (blockIdx.x*blockDim.x + threadIdx.x) >> 5;
    int lane = threadIdx.x & 31;
    if (r >= NE) return;
    float2 a[4];
    #pragma unroll
    for (int u = 0; u < 4; u++) { a[u].x = 0.f; a[u].y = 0.f; }
    bool p3 = lane < 4;
    int s = rowptr[r], e = rowptr[r+1];
    for (int idx = s; idx < e; idx++) {
        int c = __ldg(&col[idx]);
        float v = __ldg(&val[idx]);
        const __half2* xr = (const __half2*)(x + (size_t)c*DIM);
        #pragma unroll
        for (int u = 0; u < 3; u++) {
            float2 f = __half22float2(__ldg(&xr[lane + 32*u]));
            a[u].x = fmaf(v, f.x, a[u].x);
            a[u].y = fmaf(v, f.y, a[u].y);
        }
        if (p3) {
            float2 f = __half22float2(__ldg(&xr[lane + 96]));
            a[3].x = fmaf(v, f.x, a[3].x);
            a[3].y = fmaf(v, f.y, a[3].y);
        }
    }
    float m = mask[r], im = 1.f - m;
    const __half2* xs = (const __half2*)(x + (size_t)r*DIM);
    __half2* yr = (__half2*)(y + (size_t)r*DIM);
    #pragma unroll
    for (int u = 0; u < 3; u++) {
        float2 sv = __half22float2(xs[lane + 32*u]);
        yr[lane + 32*u] = __floats2half2_rn(m*sv.x + im*a[u].x, m*sv.y + im*a[u].y);
    }
    if (p3) {
        float2 sv = __half22float2(xs[lane + 96]);
        yr[lane + 96] = __floats2half2_rn(m*sv.x + im*a[3].x, m*sv.y + im*a[3].y);
    }
}

__global__ void mix_h_k(const __half* __restrict__ x, const __half* __restrict__ mp,
                        const float* __restrict__ mask, __half* __restrict__ y) {
    int idx = blockIdx.x*blockDim.x + threadIdx.x;
    if (idx >= NE*100) return;
    int row = idx / 100;
    float m = mask[row], im = 1.f - m;
    float2 a = __half22float2(__ldg((const __half2*)x + idx));
    float2 b = __half22float2(__ldg((const __half2*)mp + idx));
    ((__half2*)y)[idx] = __floats2half2_rn(m*a.x + im*b.x, m*a.y + im*b.y);
}

// RESCAL -> bf16 hrb
__global__ void rescal_k(const float* __restrict__ e0, const float* __restrict__ rel_emb,
                         const int* __restrict__ sub, const int* __restrict__ rel) {
    int b = blockIdx.x;
    int j = threadIdx.x;
    __shared__ float ls[DIM];
    const float* lhs = e0 + (size_t)sub[b]*DIM;
    if (j < DIM) ls[j] = lhs[j];
    __syncthreads();
    if (j < DIM) {
        const float* R = rel_emb + (size_t)rel[b]*RELD;
        float acc = 0.f;
        #pragma unroll 4
        for (int k = 0; k < DIM; k++) acc = fmaf(ls[k], R[(size_t)k*DIM + j], acc);
        g_hrb[(size_t)b*KPAD + j] = __float2bfloat16(acc);
    }
}

// ================= launch ==================================================
extern "C" void kernel_launch(void* const* d_in, const int* in_sizes, int n_in,
                              void* d_out, int out_size) {
    const float* e0       = (const float*)d_in[0];
    const float* rel_emb  = (const float*)d_in[1];
    const float* nW1      = (const float*)d_in[2];
    const float* nb1      = (const float*)d_in[3];
    const float* nW2      = (const float*)d_in[4];
    const float* nb2      = (const float*)d_in[5];
    const float* eW1      = (const float*)d_in[6];
    const float* eb1      = (const float*)d_in[7];
    const float* eW2      = (const float*)d_in[8];
    const float* eb2      = (const float*)d_in[9];
    const int*   adj_row  = (const int*)d_in[10];
    const int*   adj_col  = (const int*)d_in[11];
    const float* adj_val  = (const float*)d_in[12];
    const int*   rw_row   = (const int*)d_in[13];
    const int*   rw_col   = (const int*)d_in[14];
    const float* rw_val   = (const float*)d_in[15];
    const float* node_eps = (const float*)d_in[16];
    const float* edge_eps = (const float*)d_in[17];
    const int*   sub      = (const int*)d_in[18];
    const int*   rel      = (const int*)d_in[19];

    int E   = in_sizes[10];
    int Erw = in_sizes[13];

    float* out        = (float*)d_out;
    float* out_scores = out;
    float* out_xnd    = out + (size_t)BATCH*NE;
    float* out_xed    = out_xnd + (size_t)NE*DIM;

    float *NMASK, *NEWEDGE;
    __half *E0H, *X1H, *X2H, *MPH, *E2H;
    int *RPA, *RPR;
    cudaGetSymbolAddress((void**)&E0H, g_e0h);
    cudaGetSymbolAddress((void**)&X1H, g_X1h);
    cudaGetSymbolAddress((void**)&X2H, g_X2h);
    cudaGetSymbolAddress((void**)&MPH, g_MPh);
    cudaGetSymbolAddress((void**)&E2H, g_E2h);
    cudaGetSymbolAddress((void**)&NMASK, g_NMASK);
    cudaGetSymbolAddress((void**)&NEWEDGE, g_NEWEDGE);
    cudaGetSymbolAddress((void**)&RPA, g_rp_adj);
    cudaGetSymbolAddress((void**)&RPR, g_rp_rw);

    static cudaStream_t s1 = nullptr, s2 = nullptr;
    static cudaEvent_t evFork0, evConv, evUV, evMP, evS1, evS2;
    if (!s1) {
        cudaStreamCreateWithFlags(&s1, cudaStreamNonBlocking);
        cudaStreamCreateWithFlags(&s2, cudaStreamNonBlocking);
        cudaEventCreateWithFlags(&evFork0, cudaEventDisableTiming);
        cudaEventCreateWithFlags(&evConv,  cudaEventDisableTiming);
        cudaEventCreateWithFlags(&evUV,    cudaEventDisableTiming);
        cudaEventCreateWithFlags(&evMP,    cudaEventDisableTiming);
        cudaEventCreateWithFlags(&evS1,    cudaEventDisableTiming);
        cudaEventCreateWithFlags(&evS2,    cudaEventDisableTiming);
    }

    const int SPB = (NE*32 + 255)/256;
    const int MT  = (NE + 127)/128;

    // ---- fork point ----
    cudaEventRecord(evFork0, 0);

    // ---- main stream: prep ----
    rowptr_k<<<(NE+1+255)/256, 256>>>(rw_row, Erw, RPR);
    conv_e0_k<<<(NE*50 + 255)/256, 256>>>(e0);
    cudaEventRecord(evConv, 0);
    rowptr_k<<<(NE+1+255)/256, 256>>>(adj_row, E, RPA);
    dim3 wgrid((DIM*DIM + 255)/256, 4);
    conv_w_k<<<wgrid, 256>>>(nW1, eW1);

    // ---- s1: rescal -> scores ----
    cudaStreamWaitEvent(s1, evFork0, 0);
    rescal_k<<<BATCH, 256, 0, s1>>>(e0, rel_emb, sub, rel);
    cudaStreamWaitEvent(s1, evConv, 0);
    dim3 sgrid((NE + 63)/64, BATCH/128);
    scores_mm_k<<<sgrid, 256, 0, s1>>>(out_scores);
    cudaEventRecord(evS1, s1);

    // ---- s2: edge-branch rw propagation (fp16) ----
    cudaStreamWaitEvent(s2, evConv, 0);
    spmm_hh<<<SPB, 256, 0, s2>>>(RPR, rw_col, rw_val, E0H, MPH);
    cudaEventRecord(evMP, s2);
    spmm_hh<<<SPB, 256, 0, s2>>>(RPR, rw_col, rw_val, MPH, E2H);

    // ---- main: UV half first, node half second ----
    dim3 mgrid(MT, 4, 2);
    mm_e0w_k<<<mgrid, 256>>>(nb1, eb1, nW2, 2);
    cudaEventRecord(evUV, 0);
    mm_e0w_k<<<mgrid, 256>>>(nb1, eb1, nW2, 0);
    gate_fin_k<<<(2*NE + 255)/256, 256>>>(nb2, node_eps, NMASK);

    // ---- s2: edge gate + final edge spmm ----
    cudaStreamWaitEvent(s2, evUV, 0);
    edge_gate_row_k<<<SPB, 256, 0, s2>>>(RPA, adj_col, adj_val,
                                         eW2 + DIM, eb2 + 1, edge_eps + E, NEWEDGE);
    spmm_hf<<<SPB, 256, 0, s2>>>(RPA, adj_col, NEWEDGE, E2H, out_xed);
    cudaEventRecord(evS2, s2);

    // ---- main: node-drop branch (fp16 intermediates) ----
    cudaStreamWaitEvent(0, evMP, 0);
    mix_h_k<<<(NE*100 + 255)/256, 256>>>(E0H, MPH, NMASK, X1H);
    spmm_hh<<<SPB, 256>>>(RPA, adj_col, adj_val, X1H, X2H);
    spmm_mix_hh<<<SPB, 256>>>(RPR, rw_col, rw_val, X2H, NMASK + NE, X1H);
    spmm_hf<<<SPB, 256>>>(RPA, adj_col, adj_val, X1H, out_xnd);

    // ---- join ----
    cudaStreamWaitEvent(0, evS1, 0);
    cudaStreamWaitEvent(0, evS2, 0);
}

// round 16
// speedup vs baseline: 1.1250x; 1.0093x over previous
#include <cuda_runtime.h>
#include <cuda_bf16.h>
#include <cuda_fp16.h>
#include <math.h>
#include <stdint.h>

#define NE    50000
#define DIM   200
#define BATCH 1024
#define EMAX  400000
#define RELD  40000
#define KPAD  256
#define NPAD  256

// ---------------- scratch (zero-init => pad regions stay 0)
__device__ __align__(16) __nv_bfloat16 g_e0b[(size_t)NE*KPAD];
__device__ __align__(16) __nv_bfloat16 g_hrb[(size_t)BATCH*KPAD];
__device__ __align__(16) __nv_bfloat16 g_Wtb[(size_t)4*NPAD*KPAD];
__device__ __align__(16) __nv_bfloat16 g_Ub[(size_t)NE*DIM];
__device__ __align__(16) __nv_bfloat16 g_Vb[(size_t)NE*DIM];
__device__ __align__(16) float g_PL[(size_t)2*NE*8];
__device__ __align__(16) __half g_e0h[(size_t)NE*DIM];
__device__ __align__(16) __half g_X1h[(size_t)NE*DIM];
__device__ __align__(16) __half g_X2h[(size_t)NE*DIM];
__device__ __align__(16) __half g_MPh[(size_t)NE*DIM];
__device__ __align__(16) __half g_E2h[(size_t)NE*DIM];
__device__ float g_NMASK[2*NE];
__device__ float g_NEWEDGE[EMAX];
__device__ int   g_rp_adj[NE+1];
__device__ int   g_rp_rw [NE+1];

// ================= helpers =================
__device__ __forceinline__ uint32_t smem_u32(const void* p) {
    uint32_t a;
    asm("{ .reg .u64 t; cvta.to.shared.u64 t, %1; cvt.u32.u64 %0, t; }" : "=r"(a) : "l"(p));
    return a;
}
#define SW128(o) ((o) ^ (((o) >> 3) & 0x70))

__device__ __forceinline__ void ldmx4(uint32_t* r, uint32_t addr) {
    asm volatile("ldmatrix.sync.aligned.m8n8.x4.shared.b16 {%0,%1,%2,%3}, [%4];"
        : "=r"(r[0]), "=r"(r[1]), "=r"(r[2]), "=r"(r[3]) : "r"(addr));
}
__device__ __forceinline__ void mma16816(float* c, const uint32_t* a, const uint32_t* b) {
    asm volatile("mma.sync.aligned.m16n8k16.row.col.f32.bf16.bf16.f32 "
        "{%0,%1,%2,%3}, {%4,%5,%6,%7}, {%8,%9}, {%0,%1,%2,%3};"
        : "+f"(c[0]), "+f"(c[1]), "+f"(c[2]), "+f"(c[3])
        : "r"(a[0]), "r"(a[1]), "r"(a[2]), "r"(a[3]), "r"(b[0]), "r"(b[1]));
}
__device__ __forceinline__ void cpa16(uint32_t dst, const void* src) {
    asm volatile("cp.async.cg.shared.global [%0], [%1], 16;" :: "r"(dst), "l"(src));
}
#define CPA_COMMIT() asm volatile("cp.async.commit_group;" ::: "memory")
#define CPA_WAIT(n)  asm volatile("cp.async.wait_group %0;" :: "n"(n) : "memory")

__device__ __forceinline__ float gate_fn(float logits, float u) {
    const float bias = 1e-4f;
    float eps = (2.f*bias - 1.f)*u + (1.f - bias);
    float t = 2.f*(__logf(eps) - __logf(1.f - eps) + logits);
    return 1.f/(1.f + __expf(-t));
}
__device__ __forceinline__ float warp_sum(float v) {
    #pragma unroll
    for (int o = 16; o; o >>= 1) v += __shfl_xor_sync(0xffffffffu, v, o);
    return v;
}

// ================= conversion kernels =================
__global__ void conv_e0_k(const float* __restrict__ e0) {
    int t = blockIdx.x*blockDim.x + threadIdx.x;
    if (t >= NE*50) return;
    int row = t/50, k = (t%50)*4;
    float4 v = *(const float4*)(e0 + (size_t)row*DIM + k);
    __nv_bfloat162 p0, p1;
    p0.x = __float2bfloat16(v.x); p0.y = __float2bfloat16(v.y);
    p1.x = __float2bfloat16(v.z); p1.y = __float2bfloat16(v.w);
    __nv_bfloat16* d = g_e0b + (size_t)row*KPAD + k;
    *(__nv_bfloat162*)(d)     = p0;
    *(__nv_bfloat162*)(d + 2) = p1;
    __half2 h0 = __floats2half2_rn(v.x, v.y);
    __half2 h1 = __floats2half2_rn(v.z, v.w);
    __half* dh = g_e0h + (size_t)row*DIM + k;
    *(__half2*)(dh)     = h0;
    *(__half2*)(dh + 2) = h1;
}

__global__ void conv_w_k(const float* __restrict__ nW1, const float* __restrict__ eW1) {
    int inst = blockIdx.y;
    int t = blockIdx.x*blockDim.x + threadIdx.x;
    if (t >= DIM*DIM) return;
    const float* src;
    if (inst == 0)      src = nW1;
    else if (inst == 1) src = nW1 + RELD;
    else if (inst == 2) src = eW1 + 2*RELD;
    else                src = eW1 + 3*RELD;
    int n = t/DIM, k = t%DIM;
    g_Wtb[(size_t)inst*NPAD*KPAD + (size_t)n*KPAD + k] = __float2bfloat16(src[(size_t)k*DIM + n]);
}

// ================= HMMA machinery ==========================================
struct MmaCtx {
    int aAtom0, aAtom1, aLine0, aLine1, aKadd;
    int bAtom0, bAtom1, bLine0, bLine1, bKadd;
};
__device__ __forceinline__ void mma_setup(MmaCtx& cx, int tid) {
    int lane = tid & 31, i = lane >> 3, rr = lane & 7;
    int w = tid >> 5;
    int wm = w >> 1, wn = w & 1;
    int ar0 = wm*32 + (i&1)*8 + rr;
    int ar1 = ar0 + 16;
    int br0 = wn*32 + (i>>1)*8 + rr;
    int br1 = br0 + 16;
    cx.aAtom0 = (ar0>>3)*1024; cx.aLine0 = (ar0&7)*128;
    cx.aAtom1 = (ar1>>3)*1024; cx.aLine1 = (ar1&7)*128;
    cx.aKadd = (i>>1)*16;
    cx.bAtom0 = (br0>>3)*1024; cx.bLine0 = (br0&7)*128;
    cx.bAtom1 = (br1>>3)*1024; cx.bLine1 = (br1&7)*128;
    cx.bKadd = (i&1)*16;
}
__device__ __forceinline__ void mma_chunk(const MmaCtx& cx, uint32_t aA, uint32_t aB,
                                          float acc[2][4][4], int ksn) {
    #pragma unroll
    for (int ks = 0; ks < 4; ks++) {
        if (ks >= ksn) break;
        int kb = ks*32;
        uint32_t a0[4], a1[4], b0[4], b1[4];
        ldmx4(a0, aA + cx.aAtom0 + SW128(cx.aLine0 + kb + cx.aKadd));
        ldmx4(a1, aA + cx.aAtom1 + SW128(cx.aLine1 + kb + cx.aKadd));
        ldmx4(b0, aB + cx.bAtom0 + SW128(cx.bLine0 + kb + cx.bKadd));
        ldmx4(b1, aB + cx.bAtom1 + SW128(cx.bLine1 + kb + cx.bKadd));
        mma16816(acc[0][0], a0, b0);
        mma16816(acc[0][1], a0, b0 + 2);
        mma16816(acc[0][2], a0, b1);
        mma16816(acc[0][3], a0, b1 + 2);
        mma16816(acc[1][0], a1, b0);
        mma16816(acc[1][1], a1, b0 + 2);
        mma16816(acc[1][2], a1, b1);
        mma16816(acc[1][3], a1, b1 + 2);
    }
}
__device__ __forceinline__ void load_a128_async(uint32_t sA, const __nv_bfloat16* Ag,
                                                int row0, int rmax, int c, int tid) {
    #pragma unroll
    for (int i = 0; i < 4; i++) {
        int idx = tid + i*256;
        int r = idx >> 3, q = idx & 7;
        int gr = row0 + r; if (gr >= rmax) gr = 0;
        uint32_t off = (uint32_t)((r>>3)*1024) + SW128((uint32_t)((r&7)*128 + q*16));
        cpa16(sA + off, Ag + (size_t)gr*KPAD + c*64 + q*8);
    }
}
__device__ __forceinline__ void load_b64_async(uint32_t sB, const __nv_bfloat16* Bg,
                                               int row0, int rmax, int c, int tid) {
    #pragma unroll
    for (int i = 0; i < 2; i++) {
        int idx = tid + i*256;
        int r = idx >> 3, q = idx & 7;
        int gr = row0 + r; if (gr >= rmax) gr = 0;
        uint32_t off = (uint32_t)((r>>3)*1024) + SW128((uint32_t)((r&7)*128 + q*16));
        cpa16(sB + off, Bg + (size_t)gr*KPAD + c*64 + q*8);
    }
}
// tail chunk loaders: only q=0,1 (cols c*64 .. c*64+15)
__device__ __forceinline__ void load_a128_tail(uint32_t sA, const __nv_bfloat16* Ag,
                                               int row0, int rmax, int c, int tid) {
    int r = tid >> 1, q = tid & 1;
    int gr = row0 + r; if (gr >= rmax) gr = 0;
    uint32_t off = (uint32_t)((r>>3)*1024) + SW128((uint32_t)((r&7)*128 + q*16));
    cpa16(sA + off, Ag + (size_t)gr*KPAD + c*64 + q*8);
}
__device__ __forceinline__ void load_b64_tail(uint32_t sB, const __nv_bfloat16* Bg,
                                              int row0, int rmax, int c, int tid) {
    if (tid < 128) {
        int r = tid >> 1, q = tid & 1;
        int gr = row0 + r; if (gr >= rmax) gr = 0;
        uint32_t off = (uint32_t)((r>>3)*1024) + SW128((uint32_t)((r&7)*128 + q*16));
        cpa16(sB + off, Bg + (size_t)gr*KPAD + c*64 + q*8);
    }
}

// ================= GEMM 1: e0 @ W; split by inst0; K=208 truncated =========
__global__ void __launch_bounds__(256) mm_e0w_k(
    const float* __restrict__ nb1, const float* __restrict__ eb1,
    const float* __restrict__ nW2, int inst0)
{
    __shared__ __align__(1024) uint8_t sA[2][16384];
    __shared__ __align__(1024) uint8_t sB[2][8192];
    int bm = blockIdx.x, nt64 = blockIdx.y, inst = inst0 + blockIdx.z;
    int tid = threadIdx.x;
    uint32_t aA0 = smem_u32(sA[0]), aA1 = smem_u32(sA[1]);
    uint32_t aB0 = smem_u32(sB[0]), aB1 = smem_u32(sB[1]);

    MmaCtx cx; mma_setup(cx, tid);
    float acc[2][4][4];
    #pragma unroll
    for (int a = 0; a < 2; a++)
        #pragma unroll
        for (int b = 0; b < 4; b++)
            #pragma unroll
            for (int q = 0; q < 4; q++) acc[a][b][q] = 0.f;

    const __nv_bfloat16* Bg = g_Wtb + (size_t)inst*NPAD*KPAD;

    load_a128_async(aA0, g_e0b, bm*128, NE, 0, tid);
    load_b64_async (aB0, Bg, nt64*64, NPAD, 0, tid);
    CPA_COMMIT();
    #pragma unroll
    for (int c = 0; c < 4; c++) {
        uint32_t curA = (c & 1) ? aA1 : aA0, curB = (c & 1) ? aB1 : aB0;
        if (c + 1 < 4) {
            uint32_t nxtA = ((c+1) & 1) ? aA1 : aA0, nxtB = ((c+1) & 1) ? aB1 : aB0;
            if (c + 1 < 3) {
                load_a128_async(nxtA, g_e0b, bm*128, NE, c+1, tid);
                load_b64_async (nxtB, Bg, nt64*64, NPAD, c+1, tid);
            } else {
                load_a128_tail(nxtA, g_e0b, bm*128, NE, 3, tid);
                load_b64_tail (nxtB, Bg, nt64*64, NPAD, 3, tid);
            }
            CPA_COMMIT();
            CPA_WAIT(1);
        } else {
            CPA_WAIT(0);
        }
        __syncthreads();
        mma_chunk(cx, curA, curB, acc, (c < 3) ? 4 : 1);
        __syncthreads();
    }

    int lane = tid & 31, w = tid >> 5;
    int wm = w >> 1, wn = w & 1;
    int mrow = lane >> 2, ncol = (lane & 3)*2;
    int nbase = nt64*64 + wn*32;

    if (inst < 2) {
        const float* bias = nb1 + inst*DIM;
        const float* W2 = nW2 + inst*DIM;
        int seg = nt64*2 + wn;
        #pragma unroll
        for (int mt = 0; mt < 2; mt++) {
            float p0 = 0.f, p1 = 0.f;
            #pragma unroll
            for (int nt = 0; nt < 4; nt++) {
                int n = nbase + nt*8 + ncol;
                float b0 = 0.f, b1v = 0.f, w0 = 0.f, w1 = 0.f;
                if (n < DIM)     { b0 = bias[n];   w0 = W2[n];   }
                if (n + 1 < DIM) { b1v = bias[n+1]; w1 = W2[n+1]; }
                p0 = fmaf(fmaxf(acc[mt][nt][0] + b0, 0.f), w0, p0);
                p0 = fmaf(fmaxf(acc[mt][nt][1] + b1v, 0.f), w1, p0);
                p1 = fmaf(fmaxf(acc[mt][nt][2] + b0, 0.f), w0, p1);
                p1 = fmaf(fmaxf(acc[mt][nt][3] + b1v, 0.f), w1, p1);
            }
            p0 += __shfl_xor_sync(0xffffffffu, p0, 1);
            p0 += __shfl_xor_sync(0xffffffffu, p0, 2);
            p1 += __shfl_xor_sync(0xffffffffu, p1, 1);
            p1 += __shfl_xor_sync(0xffffffffu, p1, 2);
            if ((lane & 3) == 0) {
                int m0 = bm*128 + wm*32 + mt*16 + mrow;
                if (m0 < NE)     g_PL[((size_t)inst*NE + m0)*8 + seg] = p0;
                if (m0 + 8 < NE) g_PL[((size_t)inst*NE + m0 + 8)*8 + seg] = p1;
            }
        }
    } else {
        __nv_bfloat16* C = (inst == 2) ? g_Ub : g_Vb;
        const float* bias = (inst == 3) ? (eb1 + DIM) : nullptr;
        #pragma unroll
        for (int mt = 0; mt < 2; mt++) {
            int m = bm*128 + wm*32 + mt*16 + mrow;
            if (m >= NE) continue;
            #pragma unroll
            for (int nt = 0; nt < 4; nt++) {
                int n = nbase + nt*8 + ncol;
                if (n >= DIM) continue;
                float b0 = bias ? bias[n] : 0.f, b1 = bias ? bias[n+1] : 0.f;
                __nv_bfloat162 p, q;
                p.x = __float2bfloat16(acc[mt][nt][0] + b0);
                p.y = __float2bfloat16(acc[mt][nt][1] + b1);
                q.x = __float2bfloat16(acc[mt][nt][2] + b0);
                q.y = __float2bfloat16(acc[mt][nt][3] + b1);
                *(__nv_bfloat162*)(C + (size_t)m*DIM + n) = p;
                if (m + 8 < NE) *(__nv_bfloat162*)(C + (size_t)(m+8)*DIM + n) = q;
            }
        }
    }
}

// gate finalize
__global__ void gate_fin_k(const float* __restrict__ nb2, const float* __restrict__ eps,
                           float* __restrict__ mask) {
    int idx = blockIdx.x*blockDim.x + threadIdx.x;
    if (idx >= 2*NE) return;
    int inst = idx / NE;
    const float* p = g_PL + (size_t)idx*8;
    float4 a = *(const float4*)p;
    float4 b = *(const float4*)(p + 4);
    float s = ((a.x + a.y) + (a.z + a.w)) + ((b.x + b.y) + (b.z + b.w));
    mask[idx] = gate_fn(s + nb2[inst], eps[idx]);
}

// ================= GEMM 2: scores; B cached in smem, 2 M-tiles per block ===
// dynamic smem 64KB: B slots [4][8192] at 0, A double buffer at 32768/49152
__global__ void __launch_bounds__(256) scores_mm_k(float* __restrict__ out)
{
    extern __shared__ __align__(1024) uint8_t smem[];
    int bx = blockIdx.x, by = blockIdx.y;   // by covers m-tiles 2*by, 2*by+1
    int tid = threadIdx.x;
    uint32_t aB  = smem_u32(smem);
    uint32_t aA0 = smem_u32(smem + 32768), aA1 = smem_u32(smem + 49152);

    MmaCtx cx; mma_setup(cx, tid);

    // preload entire truncated B tile (chunks 0-2 full + tail)
    load_b64_async(aB,           g_e0b, bx*64, NE, 0, tid);
    load_b64_async(aB + 8192,    g_e0b, bx*64, NE, 1, tid);
    load_b64_async(aB + 16384,   g_e0b, bx*64, NE, 2, tid);
    load_b64_tail (aB + 24576,   g_e0b, bx*64, NE, 3, tid);
    CPA_COMMIT();

    int lane = tid & 31, w = tid >> 5;
    int wm = w >> 1, wn = w & 1;
    int mrow = lane >> 2, ncol = (lane & 3)*2;

    #pragma unroll
    for (int h = 0; h < 2; h++) {
        int mbase = (by*2 + h)*128;
        float acc[2][4][4];
        #pragma unroll
        for (int a = 0; a < 2; a++)
            #pragma unroll
            for (int b = 0; b < 4; b++)
                #pragma unroll
                for (int q = 0; q < 4; q++) acc[a][b][q] = 0.f;

        load_a128_async(aA0, g_hrb, mbase, BATCH, 0, tid);
        CPA_COMMIT();
        #pragma unroll
        for (int c = 0; c < 4; c++) {
            uint32_t curA = (c & 1) ? aA1 : aA0;
            if (c + 1 < 4) {
                uint32_t nxtA = ((c+1) & 1) ? aA1 : aA0;
                if (c + 1 < 3) load_a128_async(nxtA, g_hrb, mbase, BATCH, c+1, tid);
                else           load_a128_tail (nxtA, g_hrb, mbase, BATCH, 3, tid);
                CPA_COMMIT();
                CPA_WAIT(1);
            } else {
                CPA_WAIT(0);
            }
            __syncthreads();
            mma_chunk(cx, curA, aB + c*8192, acc, (c < 3) ? 4 : 1);
            __syncthreads();
        }

        #pragma unroll
        for (int mt = 0; mt < 2; mt++) {
            int m = mbase + wm*32 + mt*16 + mrow;
            #pragma unroll
            for (int nt = 0; nt < 4; nt++) {
                int n = bx*64 + wn*32 + nt*8 + ncol;
                if (n < NE) {
                    float2 v01, v23;
                    v01.x = 1.f/(1.f + __expf(-acc[mt][nt][0]));
                    v01.y = 1.f/(1.f + __expf(-acc[mt][nt][1]));
                    v23.x = 1.f/(1.f + __expf(-acc[mt][nt][2]));
                    v23.y = 1.f/(1.f + __expf(-acc[mt][nt][3]));
                    *(float2*)(out + (size_t)m*NE + n) = v01;
                    *(float2*)(out + (size_t)(m+8)*NE + n) = v23;
                }
            }
        }
        __syncthreads();   // A buffers free before next half's loads
    }
}

// ================= support kernels =================
__global__ void rowptr_k(const int* __restrict__ row, int nnz, int* __restrict__ rowptr) {
    int n = blockIdx.x*blockDim.x + threadIdx.x;
    if (n > NE) return;
    int lo = 0, hi = nnz;
    while (lo < hi) { int mid = (lo+hi) >> 1; if (row[mid] < n) lo = mid+1; else hi = mid; }
    rowptr[n] = lo;
}

// edge gate: warp per ROW; U row + W2 cached
__global__ void edge_gate_row_k(const int* __restrict__ rowptr, const int* __restrict__ col,
                                const float* __restrict__ adj_val,
                                const float* __restrict__ W2, const float* __restrict__ b2,
                                const float* __restrict__ eps, float* __restrict__ new_edge) {
    int r = (blockIdx.x*blockDim.x + threadIdx.x) >> 5;
    int lane = threadIdx.x & 31;
    if (r >= NE) return;
    int s = rowptr[r], e = rowptr[r+1];
    if (s >= e) return;

    uint4 uu = {0,0,0,0};
    float4 w01 = {0,0,0,0}, w23 = {0,0,0,0};
    if (lane < 25) {
        uu  = __ldg((const uint4*)(g_Ub + (size_t)r*DIM) + lane);
        w01 = __ldg((const float4*)(W2 + lane*8));
        w23 = __ldg((const float4*)(W2 + lane*8 + 4));
    }
    float b2v = b2[0];

    for (int idx = s; idx < e; idx++) {
        int c = __ldg(&col[idx]);
        float acc = 0.f;
        if (lane < 25) {
            uint4 vv = __ldg((const uint4*)(g_Vb + (size_t)c*DIM) + lane);
            const __nv_bfloat162* up = (const __nv_bfloat162*)&uu;
            const __nv_bfloat162* vp = (const __nv_bfloat162*)&vv;
            const float* wp = (const float*)&w01;
            const float* wq = (const float*)&w23;
            #pragma unroll
            for (int t = 0; t < 2; t++) {
                __nv_bfloat162 a = up[t], b = vp[t];
                float h0 = fmaxf(__bfloat162float(a.x) + __bfloat162float(b.x), 0.f);
                float h1 = fmaxf(__bfloat162float(a.y) + __bfloat162float(b.y), 0.f);
                acc = fmaf(h0, wp[2*t], acc);
                acc = fmaf(h1, wp[2*t+1], acc);
            }
            #pragma unroll
            for (int t = 0; t < 2; t++) {
                __nv_bfloat162 a = up[2+t], b = vp[2+t];
                float h0 = fmaxf(__bfloat162float(a.x) + __bfloat162float(b.x), 0.f);
                float h1 = fmaxf(__bfloat162float(a.y) + __bfloat162float(b.y), 0.f);
                acc = fmaf(h0, wq[2*t], acc);
                acc = fmaf(h1, wq[2*t+1], acc);
            }
        }
        acc = warp_sum(acc);
        if (lane == 0)
            new_edge[idx] = __ldg(&adj_val[idx]) * gate_fn(acc + b2v, __ldg(&eps[idx]));
    }
}

// ------- fp16 SpMM family --------
__global__ void spmm_hh(const int* __restrict__ rowptr, const int* __restrict__ col,
                        const float* __restrict__ val, const __half* __restrict__ x,
                        __half* __restrict__ y) {
    int r = (blockIdx.x*blockDim.x + threadIdx.x) >> 5;
    int lane = threadIdx.x & 31;
    if (r >= NE) return;
    float2 a[4];
    #pragma unroll
    for (int u = 0; u < 4; u++) { a[u].x = 0.f; a[u].y = 0.f; }
    bool p3 = lane < 4;
    int s = rowptr[r], e = rowptr[r+1];
    for (int idx = s; idx < e; idx++) {
        int c = __ldg(&col[idx]);
        float v = __ldg(&val[idx]);
        const __half2* xr = (const __half2*)(x + (size_t)c*DIM);
        #pragma unroll
        for (int u = 0; u < 3; u++) {
            float2 f = __half22float2(__ldg(&xr[lane + 32*u]));
            a[u].x = fmaf(v, f.x, a[u].x);
            a[u].y = fmaf(v, f.y, a[u].y);
        }
        if (p3) {
            float2 f = __half22float2(__ldg(&xr[lane + 96]));
            a[3].x = fmaf(v, f.x, a[3].x);
            a[3].y = fmaf(v, f.y, a[3].y);
        }
    }
    __half2* yr = (__half2*)(y + (size_t)r*DIM);
    #pragma unroll
    for (int u = 0; u < 3; u++) yr[lane + 32*u] = __floats2half2_rn(a[u].x, a[u].y);
    if (p3) yr[lane + 96] = __floats2half2_rn(a[3].x, a[3].y);
}

__global__ void spmm_hf(const int* __restrict__ rowptr, const int* __restrict__ col,
                        const float* __restrict__ val, const __half* __restrict__ x,
                        float* __restrict__ y) {
    int r = (blockIdx.x*blockDim.x + threadIdx.x) >> 5;
    int lane = threadIdx.x & 31;
    if (r >= NE) return;
    float2 a[4];
    #pragma unroll
    for (int u = 0; u < 4; u++) { a[u].x = 0.f; a[u].y = 0.f; }
    bool p3 = lane < 4;
    int s = rowptr[r], e = rowptr[r+1];
    for (int idx = s; idx < e; idx++) {
        int c = __ldg(&col[idx]);
        float v = __ldg(&val[idx]);
        const __half2* xr = (const __half2*)(x + (size_t)c*DIM);
        #pragma unroll
        for (int u = 0; u < 3; u++) {
            float2 f = __half22float2(__ldg(&xr[lane + 32*u]));
            a[u].x = fmaf(v, f.x, a[u].x);
            a[u].y = fmaf(v, f.y, a[u].y);
        }
        if (p3) {
            float2 f = __half22float2(__ldg(&xr[lane + 96]));
            a[3].x = fmaf(v, f.x, a[3].x);
            a[3].y = fmaf(v, f.y, a[3].y);
        }
    }
    float2* yr = (float2*)(y + (size_t)r*DIM);
    #pragma unroll
    for (int u = 0; u < 3; u++) yr[lane + 32*u] = a[u];
    if (p3) yr[lane + 96] = a[3];
}

__global__ void spmm_mix_hh(const int* __restrict__ rowptr, const int* __restrict__ col,
                            const float* __restrict__ val, const __half* __restrict__ x,
                            const float* __restrict__ mask, __half* __restrict__ y) {
    int r = (blockIdx.x*blockDim.x + threadIdx.x) >> 5;
    int lane = threadIdx.x & 31;
    if (r >= NE) return;
    float2 a[4];
    #pragma unroll
    for (int u = 0; u < 4; u++) { a[u].x = 0.f; a[u].y = 0.f; }
    bool p3 = lane < 4;
    int s = rowptr[r], e = rowptr[r+1];
    for (int idx = s; idx < e; idx++) {
        int c = __ldg(&col[idx]);
        float v = __ldg(&val[idx]);
        const __half2* xr = (const __half2*)(x + (size_t)c*DIM);
        #pragma unroll
        for (int u = 0; u < 3; u++) {
            float2 f = __half22float2(__ldg(&xr[lane + 32*u]));
            a[u].x = fmaf(v, f.x, a[u].x);
            a[u].y = fmaf(v, f.y, a[u].y);
        }
        if (p3) {
            float2 f = __half22float2(__ldg(&xr[lane + 96]));
            a[3].x = fmaf(v, f.x, a[3].x);
            a[3].y = fmaf(v, f.y, a[3].y);
        }
    }
    float m = mask[r], im = 1.f - m;
    const __half2* xs = (const __half2*)(x + (size_t)r*DIM);
    __half2* yr = (__half2*)(y + (size_t)r*DIM);
    #pragma unroll
    for (int u = 0; u < 3; u++) {
        float2 sv = __half22float2(xs[lane + 32*u]);
        yr[lane + 32*u] = __floats2half2_rn(m*sv.x + im*a[u].x, m*sv.y + im*a[u].y);
    }
    if (p3) {
        float2 sv = __half22float2(xs[lane + 96]);
        yr[lane + 96] = __floats2half2_rn(m*sv.x + im*a[3].x, m*sv.y + im*a[3].y);
    }
}

__global__ void mix_h_k(const __half* __restrict__ x, const __half* __restrict__ mp,
                        const float* __restrict__ mask, __half* __restrict__ y) {
    int idx = blockIdx.x*blockDim.x + threadIdx.x;
    if (idx >= NE*100) return;
    int row = idx / 100;
    float m = mask[row], im = 1.f - m;
    float2 a = __half22float2(__ldg((const __half2*)x + idx));
    float2 b = __half22float2(__ldg((const __half2*)mp + idx));
    ((__half2*)y)[idx] = __floats2half2_rn(m*a.x + im*b.x, m*a.y + im*b.y);
}

// RESCAL -> bf16 hrb
__global__ void rescal_k(const float* __restrict__ e0, const float* __restrict__ rel_emb,
                         const int* __restrict__ sub, const int* __restrict__ rel) {
    int b = blockIdx.x;
    int j = threadIdx.x;
    __shared__ float ls[DIM];
    const float* lhs = e0 + (size_t)sub[b]*DIM;
    if (j < DIM) ls[j] = lhs[j];
    __syncthreads();
    if (j < DIM) {
        const float* R = rel_emb + (size_t)rel[b]*RELD;
        float acc = 0.f;
        #pragma unroll 4
        for (int k = 0; k < DIM; k++) acc = fmaf(ls[k], R[(size_t)k*DIM + j], acc);
        g_hrb[(size_t)b*KPAD + j] = __float2bfloat16(acc);
    }
}

// ================= launch ==================================================
extern "C" void kernel_launch(void* const* d_in, const int* in_sizes, int n_in,
                              void* d_out, int out_size) {
    const float* e0       = (const float*)d_in[0];
    const float* rel_emb  = (const float*)d_in[1];
    const float* nW1      = (const float*)d_in[2];
    const float* nb1      = (const float*)d_in[3];
    const float* nW2      = (const float*)d_in[4];
    const float* nb2      = (const float*)d_in[5];
    const float* eW1      = (const float*)d_in[6];
    const float* eb1      = (const float*)d_in[7];
    const float* eW2      = (const float*)d_in[8];
    const float* eb2      = (const float*)d_in[9];
    const int*   adj_row  = (const int*)d_in[10];
    const int*   adj_col  = (const int*)d_in[11];
    const float* adj_val  = (const float*)d_in[12];
    const int*   rw_row   = (const int*)d_in[13];
    const int*   rw_col   = (const int*)d_in[14];
    const float* rw_val   = (const float*)d_in[15];
    const float* node_eps = (const float*)d_in[16];
    const float* edge_eps = (const float*)d_in[17];
    const int*   sub      = (const int*)d_in[18];
    const int*   rel      = (const int*)d_in[19];

    int E   = in_sizes[10];
    int Erw = in_sizes[13];

    float* out        = (float*)d_out;
    float* out_scores = out;
    float* out_xnd    = out + (size_t)BATCH*NE;
    float* out_xed    = out_xnd + (size_t)NE*DIM;

    float *NMASK, *NEWEDGE;
    __half *E0H, *X1H, *X2H, *MPH, *E2H;
    int *RPA, *RPR;
    cudaGetSymbolAddress((void**)&E0H, g_e0h);
    cudaGetSymbolAddress((void**)&X1H, g_X1h);
    cudaGetSymbolAddress((void**)&X2H, g_X2h);
    cudaGetSymbolAddress((void**)&MPH, g_MPh);
    cudaGetSymbolAddress((void**)&E2H, g_E2h);
    cudaGetSymbolAddress((void**)&NMASK, g_NMASK);
    cudaGetSymbolAddress((void**)&NEWEDGE, g_NEWEDGE);
    cudaGetSymbolAddress((void**)&RPA, g_rp_adj);
    cudaGetSymbolAddress((void**)&RPR, g_rp_rw);

    static cudaStream_t s1 = nullptr, s2 = nullptr;
    static cudaEvent_t evFork0, evConv, evUV, evMP, evS1, evS2;
    if (!s1) {
        cudaStreamCreateWithFlags(&s1, cudaStreamNonBlocking);
        cudaStreamCreateWithFlags(&s2, cudaStreamNonBlocking);
        cudaEventCreateWithFlags(&evFork0, cudaEventDisableTiming);
        cudaEventCreateWithFlags(&evConv,  cudaEventDisableTiming);
        cudaEventCreateWithFlags(&evUV,    cudaEventDisableTiming);
        cudaEventCreateWithFlags(&evMP,    cudaEventDisableTiming);
        cudaEventCreateWithFlags(&evS1,    cudaEventDisableTiming);
        cudaEventCreateWithFlags(&evS2,    cudaEventDisableTiming);
        cudaFuncSetAttribute(scores_mm_k, cudaFuncAttributeMaxDynamicSharedMemorySize, 65536);
    }

    const int SPB = (NE*32 + 255)/256;
    const int MT  = (NE + 127)/128;

    // ---- fork point ----
    cudaEventRecord(evFork0, 0);

    // ---- main stream: prep ----
    rowptr_k<<<(NE+1+255)/256, 256>>>(rw_row, Erw, RPR);
    conv_e0_k<<<(NE*50 + 255)/256, 256>>>(e0);
    cudaEventRecord(evConv, 0);
    rowptr_k<<<(NE+1+255)/256, 256>>>(adj_row, E, RPA);
    dim3 wgrid((DIM*DIM + 255)/256, 4);
    conv_w_k<<<wgrid, 256>>>(nW1, eW1);

    // ---- s1: rescal -> scores ----
    cudaStreamWaitEvent(s1, evFork0, 0);
    rescal_k<<<BATCH, 256, 0, s1>>>(e0, rel_emb, sub, rel);
    cudaStreamWaitEvent(s1, evConv, 0);
    dim3 sgrid((NE + 63)/64, BATCH/256);
    scores_mm_k<<<sgrid, 256, 65536, s1>>>(out_scores);
    cudaEventRecord(evS1, s1);

    // ---- s2: edge-branch rw propagation (fp16) ----
    cudaStreamWaitEvent(s2, evConv, 0);
    spmm_hh<<<SPB, 256, 0, s2>>>(RPR, rw_col, rw_val, E0H, MPH);
    cudaEventRecord(evMP, s2);
    spmm_hh<<<SPB, 256, 0, s2>>>(RPR, rw_col, rw_val, MPH, E2H);

    // ---- main: UV half first, node half second ----
    dim3 mgrid(MT, 4, 2);
    mm_e0w_k<<<mgrid, 256>>>(nb1, eb1, nW2, 2);
    cudaEventRecord(evUV, 0);
    mm_e0w_k<<<mgrid, 256>>>(nb1, eb1, nW2, 0);
    gate_fin_k<<<(2*NE + 255)/256, 256>>>(nb2, node_eps, NMASK);

    // ---- s2: edge gate + final edge spmm ----
    cudaStreamWaitEvent(s2, evUV, 0);
    edge_gate_row_k<<<SPB, 256, 0, s2>>>(RPA, adj_col, adj_val,
                                         eW2 + DIM, eb2 + 1, edge_eps + E, NEWEDGE);
    spmm_hf<<<SPB, 256, 0, s2>>>(RPA, adj_col, NEWEDGE, E2H, out_xed);
    cudaEventRecord(evS2, s2);

    // ---- main: node-drop branch (fp16 intermediates) ----
    cudaStreamWaitEvent(0, evMP, 0);
    mix_h_k<<<(NE*100 + 255)/256, 256>>>(E0H, MPH, NMASK, X1H);
    spmm_hh<<<SPB, 256>>>(RPA, adj_col, adj_val, X1H, X2H);
    spmm_mix_hh<<<SPB, 256>>>(RPR, rw_col, rw_val, X2H, NMASK + NE, X1H);
    spmm_hf<<<SPB, 256>>>(RPA, adj_col, adj_val, X1H, out_xnd);

    // ---- join ----
    cudaStreamWaitEvent(0, evS1, 0);
    cudaStreamWaitEvent(0, evS2, 0);
}